// round 1
// baseline (speedup 1.0000x reference)
#include <cuda_runtime.h>

#define NN 50000
#define NE 1600000
#define HH 128
#define GG 256
#define BN_EPS 1e-5f

// ---------------- scratch (static device memory; no allocs allowed) --------
__device__ int   g_is64;
__device__ int   g_deg[NN];
__device__ int   g_rowoff[NN + 1];
__device__ int   g_cursor[NN];
__device__ int   g_srcs[NE];
__device__ float g_coef[NE];
__device__ float g_dinv[NN];
__device__ float g_h[NN * HH];
__device__ float g_hw[NN * HH];
__device__ float g_sums[GG * HH];
__device__ float g_cnt[GG];
__device__ float g_pk[64];
__device__ float g_Wp[64 * HH];

__device__ __forceinline__ int load_idx(const void* p, long long i, int is64) {
    if (is64) return (int)((const long long*)p)[i];
    return ((const int*)p)[i];
}

// ---------------- dtype detection for "int64" inputs ------------------------
// If the buffer is really int64 (values < 2^31), every odd int32 word is 0.
__global__ void k_detect(const void* ei) {
    const int* p = (const int*)ei;
    int allz = 1;
    for (int i = 1; i < 256; i += 2) {
        if (p[i] != 0) { allz = 0; break; }
    }
    g_is64 = allz;
}

// ---------------- degree / CSR build ----------------------------------------
__global__ void k_zero_deg() {
    int i = blockIdx.x * blockDim.x + threadIdx.x;
    if (i < NN) g_deg[i] = 0;
}

__global__ void k_deg_count(const void* ei) {
    int e = blockIdx.x * blockDim.x + threadIdx.x;
    if (e < NE) {
        int d = load_idx(ei, (long long)NE + e, g_is64);
        atomicAdd(&g_deg[d], 1);
    }
}

// single-block scan over N=50000 (49 tiles of 1024), also computes dinv
__global__ void k_scan() {
    __shared__ int sh[1024];
    int tid = threadIdx.x;
    int carry = 0;
    const int ntiles = (NN + 1023) / 1024;
    for (int t = 0; t < ntiles; t++) {
        int i = t * 1024 + tid;
        int v = (i < NN) ? g_deg[i] : 0;
        sh[tid] = v;
        __syncthreads();
        #pragma unroll
        for (int off = 1; off < 1024; off <<= 1) {
            int a = (tid >= off) ? sh[tid - off] : 0;
            __syncthreads();
            sh[tid] += a;
            __syncthreads();
        }
        if (i < NN) {
            g_rowoff[i] = carry + sh[tid] - v;   // exclusive prefix
            g_dinv[i]   = rsqrtf((float)v + 1.0f); // +1 self loop
        }
        carry += sh[1023];
        __syncthreads();
    }
    if (tid == 0) g_rowoff[NN] = carry;
}

__global__ void k_copy_cursor() {
    int i = blockIdx.x * blockDim.x + threadIdx.x;
    if (i < NN) g_cursor[i] = g_rowoff[i];
}

__global__ void k_scatter(const void* ei) {
    int e = blockIdx.x * blockDim.x + threadIdx.x;
    if (e < NE) {
        int is64 = g_is64;
        int s = load_idx(ei, e, is64);
        int d = load_idx(ei, (long long)NE + e, is64);
        int pos = atomicAdd(&g_cursor[d], 1);
        g_srcs[pos] = s;
        g_coef[pos] = g_dinv[s] * g_dinv[d];
    }
}

// ---------------- GEMMs -----------------------------------------------------
// layer 0: hw = x[N,7] @ W0[7,128]
__global__ void k_gemm0(const float* __restrict__ x, const float* __restrict__ W) {
    __shared__ float sx[7];
    int n = blockIdx.x;
    if (threadIdx.x < 7) sx[threadIdx.x] = x[n * 7 + threadIdx.x];
    __syncthreads();
    float acc = 0.f;
    #pragma unroll
    for (int k = 0; k < 7; k++) acc += sx[k] * W[k * HH + threadIdx.x];
    g_hw[n * HH + threadIdx.x] = acc;
}

// hw = A[N,128] @ W[128,128]; 16 rows per block, 128 threads (one per col)
__global__ void k_gemm128(const float* __restrict__ A, const float* __restrict__ W,
                          float* __restrict__ C) {
    __shared__ float sA[16][HH];
    int row0 = blockIdx.x * 16;
    int tid = threadIdx.x;
    #pragma unroll
    for (int r = 0; r < 16; r++) sA[r][tid] = A[(row0 + r) * HH + tid];
    __syncthreads();
    float acc[16];
    #pragma unroll
    for (int r = 0; r < 16; r++) acc[r] = 0.f;
    for (int k = 0; k < HH; k += 4) {
        float w0 = W[(k + 0) * HH + tid];
        float w1 = W[(k + 1) * HH + tid];
        float w2 = W[(k + 2) * HH + tid];
        float w3 = W[(k + 3) * HH + tid];
        #pragma unroll
        for (int r = 0; r < 16; r++) {
            float4 a = *(const float4*)&sA[r][k];
            acc[r] += a.x * w0 + a.y * w1 + a.z * w2 + a.w * w3;
        }
    }
    #pragma unroll
    for (int r = 0; r < 16; r++) C[(row0 + r) * HH + tid] = acc[r];
}

// ---------------- fused aggregation + bias + BN + ReLU ----------------------
// warp per node; lane handles 4 consecutive features (float4)
__global__ void k_agg(const float* __restrict__ hw, float* __restrict__ hout,
                      const float* __restrict__ bias,
                      const float* __restrict__ gamma, const float* __restrict__ beta,
                      const float* __restrict__ mean,  const float* __restrict__ var) {
    int w = (blockIdx.x * blockDim.x + threadIdx.x) >> 5;
    int lane = threadIdx.x & 31;
    if (w >= NN) return;
    int v = w;
    float di = g_dinv[v];
    float c0 = di * di;
    int j = lane * 4;
    float4 a = *(const float4*)&hw[v * HH + j];
    float ax = c0 * a.x, ay = c0 * a.y, az = c0 * a.z, aw = c0 * a.w;
    int e0 = g_rowoff[v], e1 = g_rowoff[v + 1];
    for (int e = e0; e < e1; e++) {
        int s = g_srcs[e];
        float c = g_coef[e];
        float4 t = *(const float4*)&hw[s * HH + j];
        ax += c * t.x; ay += c * t.y; az += c * t.z; aw += c * t.w;
    }
    float4 b4 = *(const float4*)&bias[j];
    float4 g4 = *(const float4*)&gamma[j];
    float4 be4 = *(const float4*)&beta[j];
    float4 m4 = *(const float4*)&mean[j];
    float4 v4 = *(const float4*)&var[j];
    float4 o;
    o.x = fmaxf(g4.x * (ax + b4.x - m4.x) * rsqrtf(v4.x + BN_EPS) + be4.x, 0.f);
    o.y = fmaxf(g4.y * (ay + b4.y - m4.y) * rsqrtf(v4.y + BN_EPS) + be4.y, 0.f);
    o.z = fmaxf(g4.z * (az + b4.z - m4.z) * rsqrtf(v4.z + BN_EPS) + be4.z, 0.f);
    o.w = fmaxf(g4.w * (aw + b4.w - m4.w) * rsqrtf(v4.w + BN_EPS) + be4.w, 0.f);
    *(float4*)&hout[v * HH + j] = o;
}

// ---------------- pooling ----------------------------------------------------
__global__ void k_zero_pool() {
    int i = blockIdx.x * blockDim.x + threadIdx.x;
    if (i < GG * HH) g_sums[i] = 0.f;
    if (i < GG) g_cnt[i] = 0.f;
}

__global__ void k_pool(const void* batch) {
    int w = (blockIdx.x * blockDim.x + threadIdx.x) >> 5;
    int lane = threadIdx.x & 31;
    if (w >= NN) return;
    int g = load_idx(batch, w, g_is64);
    int j = lane * 4;
    float4 t = *(const float4*)&g_h[w * HH + j];
    atomicAdd(&g_sums[g * HH + j + 0], t.x);
    atomicAdd(&g_sums[g * HH + j + 1], t.y);
    atomicAdd(&g_sums[g * HH + j + 2], t.z);
    atomicAdd(&g_sums[g * HH + j + 3], t.w);
    if (lane == 0) atomicAdd(&g_cnt[g], 1.f);
}

// ---------------- pocket MLP + bilinear weight contraction -------------------
__global__ void k_small(const float* __restrict__ pf,
                        const float* __restrict__ W1, const float* __restrict__ b1,
                        const float* __restrict__ W2, const float* __restrict__ b2,
                        const float* __restrict__ bilW) {
    __shared__ float t1[64];
    __shared__ float spk[64];
    int tid = threadIdx.x;
    if (tid < 64) {
        float acc = b1[tid];
        for (int k = 0; k < 28; k++) acc += pf[k] * W1[k * 64 + tid];
        t1[tid] = fmaxf(acc, 0.f);
    }
    __syncthreads();
    if (tid < 64) {
        float acc = b2[tid];
        for (int jj = 0; jj < 64; jj++) acc += t1[jj] * W2[jj * 64 + tid];
        spk[tid] = acc;
        g_pk[tid] = acc;
    }
    __syncthreads();
    // Wp[o][i] = sum_j bilW[o,i,j] * pk[j]
    for (int idx = tid; idx < 64 * HH; idx += blockDim.x) {
        int o = idx / HH, i2 = idx % HH;
        const float* wrow = bilW + ((long long)o * HH + i2) * 64;
        float acc = 0.f;
        #pragma unroll 8
        for (int jj = 0; jj < 64; jj++) acc += wrow[jj] * spk[jj];
        g_Wp[o * HH + i2] = acc;
    }
}

// ---------------- bilinear + classifier per graph ----------------------------
__global__ void k_final(const float* __restrict__ bil_b,
                        const float* __restrict__ cW1, const float* __restrict__ cb1,
                        const float* __restrict__ cW2, const float* __restrict__ cb2,
                        float* __restrict__ out) {
    __shared__ float lig[HH];
    __shared__ float inter[64];
    __shared__ float c1[32];
    int g = blockIdx.x;
    int tid = threadIdx.x;
    float cnt = fmaxf(g_cnt[g], 1.f);
    lig[tid]      = g_sums[g * HH + tid] / cnt;
    lig[tid + 64] = g_sums[g * HH + tid + 64] / cnt;
    __syncthreads();
    {
        float acc = bil_b[tid];
        for (int i = 0; i < HH; i++) acc += lig[i] * g_Wp[tid * HH + i];
        inter[tid] = acc;
    }
    __syncthreads();
    if (tid < 32) {
        float acc = cb1[tid];
        for (int o = 0; o < 64; o++) acc += inter[o] * cW1[o * 32 + tid];
        c1[tid] = fmaxf(acc, 0.f);
    }
    __syncthreads();
    if (tid == 0) {
        float acc = cb2[0];
        #pragma unroll
        for (int t = 0; t < 32; t++) acc += c1[t] * cW2[t];
        out[g] = acc;
    }
}

// ---------------- launch ------------------------------------------------------
extern "C" void kernel_launch(void* const* d_in, const int* in_sizes, int n_in,
                              void* d_out, int out_size) {
    const float* x       = (const float*)d_in[0];
    const void*  ei      = d_in[1];
    const void*  batch   = d_in[2];
    const float* pocket  = (const float*)d_in[3];
    const float* conv0_W = (const float*)d_in[4];
    const float* conv0_b = (const float*)d_in[5];
    const float* convs_W = (const float*)d_in[6];
    const float* convs_b = (const float*)d_in[7];
    const float* bn_g    = (const float*)d_in[8];
    const float* bn_b    = (const float*)d_in[9];
    const float* bn_m    = (const float*)d_in[10];
    const float* bn_v    = (const float*)d_in[11];
    const float* pW1     = (const float*)d_in[12];
    const float* pb1     = (const float*)d_in[13];
    const float* pW2     = (const float*)d_in[14];
    const float* pb2     = (const float*)d_in[15];
    const float* bilW    = (const float*)d_in[16];
    const float* bilb    = (const float*)d_in[17];
    const float* cW1     = (const float*)d_in[18];
    const float* cb1     = (const float*)d_in[19];
    const float* cW2     = (const float*)d_in[20];
    const float* cb2     = (const float*)d_in[21];
    float* out = (float*)d_out;

    // pointers to layer-parameter slices
    float* h  = nullptr; float* hw = nullptr;
    cudaGetSymbolAddress((void**)&h,  g_h);
    cudaGetSymbolAddress((void**)&hw, g_hw);

    const int TB = 256;
    // 1) dtype detect + CSR build
    k_detect<<<1, 1>>>(ei);
    k_zero_deg<<<(NN + TB - 1) / TB, TB>>>();
    k_deg_count<<<(NE + TB - 1) / TB, TB>>>(ei);
    k_scan<<<1, 1024>>>();
    k_copy_cursor<<<(NN + TB - 1) / TB, TB>>>();
    k_scatter<<<(NE + TB - 1) / TB, TB>>>(ei);

    int agg_blocks = (NN * 32 + TB - 1) / TB;

    // 2) layer 0: x @ W0, agg + BN0 + ReLU
    k_gemm0<<<NN, HH>>>(x, conv0_W);
    k_agg<<<agg_blocks, TB>>>(hw, h, conv0_b,
                              bn_g + 0 * HH, bn_b + 0 * HH, bn_m + 0 * HH, bn_v + 0 * HH);

    // 3) layers 1,2
    for (int l = 1; l <= 2; l++) {
        const float* W = convs_W + (long long)(l - 1) * HH * HH;
        const float* b = convs_b + (l - 1) * HH;
        k_gemm128<<<NN / 16, HH>>>(h, W, hw);
        k_agg<<<agg_blocks, TB>>>(hw, h, b,
                                  bn_g + l * HH, bn_b + l * HH, bn_m + l * HH, bn_v + l * HH);
    }

    // 4) pooling
    k_zero_pool<<<(GG * HH + TB - 1) / TB, TB>>>();
    k_pool<<<agg_blocks, TB>>>(batch);

    // 5) pocket MLP + bilinear contraction + classifier
    k_small<<<1, 128>>>(pocket, pW1, pb1, pW2, pb2, bilW);
    k_final<<<GG, 64>>>(bilb, cW1, cb1, cW2, cb2, out);
}

// round 2
// speedup vs baseline: 1.1839x; 1.1839x over previous
#include <cuda_runtime.h>

#define NN 50000
#define NE 1600000
#define HH 128
#define GG 256
#define BN_EPS 1e-5f
#define NB ((NN + 1023) / 1024)   // 49 scan blocks

// ---------------- scratch (static device memory) ----------------------------
__device__ int   g_is64;
__device__ int   g_deg[NN];
__device__ int   g_rowoff[NN + 1];
__device__ int   g_cursor[NN];
__device__ int2  g_edge[NE];          // {src, coef bits}
__device__ float g_dinv[NN];
__device__ int   g_bsum[NB];
__device__ int   g_boff[NB];
__device__ float g_h[NN * HH];
__device__ float g_hw[NN * HH];
__device__ float g_Wp[64 * HH];

__device__ __forceinline__ int load_idx(const void* p, long long i, int is64) {
    if (is64) return (int)((const long long*)p)[i];
    return ((const int*)p)[i];
}

// ---------------- dtype detection (parallel, 1 warp) -------------------------
__global__ void k_detect(const void* ei) {
    const int* p = (const int*)ei;
    int lane = threadIdx.x;
    int nz = 0;
    #pragma unroll
    for (int r = 0; r < 4; r++) {
        if (p[(lane + r * 32) * 2 + 1] != 0) nz = 1;
    }
    unsigned m = __ballot_sync(0xFFFFFFFFu, nz);
    if (lane == 0) g_is64 = (m == 0u) ? 1 : 0;
}

// ---------------- degree / CSR build -----------------------------------------
__global__ void k_zero_deg() {
    int i = blockIdx.x * blockDim.x + threadIdx.x;
    if (i < NN) g_deg[i] = 0;
}

__global__ void k_deg_count(const void* ei) {
    int e = blockIdx.x * blockDim.x + threadIdx.x;
    if (e < NE) {
        int d = load_idx(ei, (long long)NE + e, g_is64);
        atomicAdd(&g_deg[d], 1);
    }
}

// per-block (1024) scan; writes local exclusive prefix + block sums + dinv
__global__ void k_scanA() {
    int i = blockIdx.x * 1024 + threadIdx.x;
    int v = (i < NN) ? g_deg[i] : 0;
    int lane = threadIdx.x & 31, wid = threadIdx.x >> 5;
    int s = v;
    #pragma unroll
    for (int o = 1; o < 32; o <<= 1) {
        int t = __shfl_up_sync(0xFFFFFFFFu, s, o);
        if (lane >= o) s += t;
    }
    __shared__ int wsum[32];
    if (lane == 31) wsum[wid] = s;
    __syncthreads();
    if (wid == 0) {
        int t = wsum[lane];
        #pragma unroll
        for (int o = 1; o < 32; o <<= 1) {
            int u = __shfl_up_sync(0xFFFFFFFFu, t, o);
            if (lane >= o) t += u;
        }
        wsum[lane] = t;
    }
    __syncthreads();
    int incl = s + (wid > 0 ? wsum[wid - 1] : 0);
    if (i < NN) {
        g_rowoff[i] = incl - v;
        g_dinv[i]   = rsqrtf((float)v + 1.0f);
    }
    if (threadIdx.x == 1023) g_bsum[blockIdx.x] = incl;
}

__global__ void k_scanB() {
    if (threadIdx.x == 0) {
        int c = 0;
        for (int b = 0; b < NB; b++) { int t = g_bsum[b]; g_boff[b] = c; c += t; }
        g_rowoff[NN] = c;
    }
}

__global__ void k_scanC() {
    int i = blockIdx.x * 1024 + threadIdx.x;
    if (i < NN) {
        int v = g_rowoff[i] + g_boff[blockIdx.x];
        g_rowoff[i] = v;
        g_cursor[i] = v;
    }
}

__global__ void k_scatter(const void* ei) {
    int e = blockIdx.x * blockDim.x + threadIdx.x;
    if (e < NE) {
        int is64 = g_is64;
        int s = load_idx(ei, e, is64);
        int d = load_idx(ei, (long long)NE + e, is64);
        int pos = atomicAdd(&g_cursor[d], 1);
        float c = g_dinv[s] * g_dinv[d];
        g_edge[pos] = make_int2(s, __float_as_int(c));
    }
}

// ---------------- GEMMs -------------------------------------------------------
// layer 0: hw = x[N,7] @ W0[7,128]; 8 rows per block
__global__ void k_gemm0(const float* __restrict__ x, const float* __restrict__ W) {
    __shared__ float sx[8][7];
    int row0 = blockIdx.x * 8;
    int tid = threadIdx.x;
    if (tid < 56) {
        int r = tid / 7, c = tid % 7;
        int gr = row0 + r;
        sx[r][c] = (gr < NN) ? x[gr * 7 + c] : 0.f;
    }
    __syncthreads();
    #pragma unroll
    for (int r = 0; r < 8; r++) {
        int gr = row0 + r;
        if (gr < NN) {
            float acc = 0.f;
            #pragma unroll
            for (int k = 0; k < 7; k++) acc += sx[r][k] * W[k * HH + tid];
            g_hw[gr * HH + tid] = acc;
        }
    }
}

// C = A[N,128] @ W[128,128]; 64 rows/block, 256 threads, each 8 rows x 4 cols
__global__ void __launch_bounds__(256) k_gemm128(const float* __restrict__ A,
                                                 const float* __restrict__ W,
                                                 float* __restrict__ C) {
    __shared__ float sA[64][HH];
    int row0 = blockIdx.x * 64;
    int tid = threadIdx.x;
    // stage A (64x128 floats = 2048 float4, 8 per thread)
    for (int i = tid; i < 64 * 32; i += 256) {
        int r = i >> 5, c4 = i & 31;
        int gr = row0 + r;
        float4 v = (gr < NN) ? *(const float4*)&A[gr * HH + c4 * 4]
                             : make_float4(0.f, 0.f, 0.f, 0.f);
        *(float4*)&sA[r][c4 * 4] = v;
    }
    __syncthreads();
    int cg = tid & 31;       // cols 4*cg .. 4*cg+3  (lane -> coalesced W float4)
    int rg = tid >> 5;       // rows 8*rg .. 8*rg+7  (warp-uniform -> LDS broadcast)
    float acc[8][4] = {};
    #pragma unroll 4
    for (int k = 0; k < HH; k++) {
        float4 w = __ldg((const float4*)&W[k * HH + cg * 4]);
        #pragma unroll
        for (int r = 0; r < 8; r++) {
            float a = sA[rg * 8 + r][k];
            acc[r][0] += a * w.x;
            acc[r][1] += a * w.y;
            acc[r][2] += a * w.z;
            acc[r][3] += a * w.w;
        }
    }
    #pragma unroll
    for (int r = 0; r < 8; r++) {
        int gr = row0 + rg * 8 + r;
        if (gr < NN) {
            float4 o = make_float4(acc[r][0], acc[r][1], acc[r][2], acc[r][3]);
            *(float4*)&C[gr * HH + cg * 4] = o;
        }
    }
}

// ---------------- fused aggregation + bias + BN + ReLU ------------------------
__global__ void k_agg(const float* __restrict__ hw, float* __restrict__ hout,
                      const float* __restrict__ bias,
                      const float* __restrict__ gamma, const float* __restrict__ beta,
                      const float* __restrict__ mean,  const float* __restrict__ var) {
    int w = (blockIdx.x * blockDim.x + threadIdx.x) >> 5;
    int lane = threadIdx.x & 31;
    if (w >= NN) return;
    int v = w;
    float di = g_dinv[v];
    float c0 = di * di;
    int j = lane * 4;
    float4 a = *(const float4*)&hw[v * HH + j];
    float ax = c0 * a.x, ay = c0 * a.y, az = c0 * a.z, aw = c0 * a.w;
    int e0 = g_rowoff[v], e1 = g_rowoff[v + 1];
    for (int e = e0; e < e1; e++) {
        int2 ed = __ldg(&g_edge[e]);               // warp-broadcast
        float c = __int_as_float(ed.y);
        float4 t = __ldg((const float4*)&hw[ed.x * HH + j]);
        ax += c * t.x; ay += c * t.y; az += c * t.z; aw += c * t.w;
    }
    float4 b4 = *(const float4*)&bias[j];
    float4 g4 = *(const float4*)&gamma[j];
    float4 be4 = *(const float4*)&beta[j];
    float4 m4 = *(const float4*)&mean[j];
    float4 v4 = *(const float4*)&var[j];
    float4 o;
    o.x = fmaxf(g4.x * (ax + b4.x - m4.x) * rsqrtf(v4.x + BN_EPS) + be4.x, 0.f);
    o.y = fmaxf(g4.y * (ay + b4.y - m4.y) * rsqrtf(v4.y + BN_EPS) + be4.y, 0.f);
    o.z = fmaxf(g4.z * (az + b4.z - m4.z) * rsqrtf(v4.z + BN_EPS) + be4.z, 0.f);
    o.w = fmaxf(g4.w * (aw + b4.w - m4.w) * rsqrtf(v4.w + BN_EPS) + be4.w, 0.f);
    *(float4*)&hout[v * HH + j] = o;
}

// ---------------- pocket MLP + bilinear weight contraction --------------------
__global__ void k_small(const float* __restrict__ pf,
                        const float* __restrict__ W1, const float* __restrict__ b1,
                        const float* __restrict__ W2, const float* __restrict__ b2,
                        const float* __restrict__ bilW) {
    __shared__ float t1[64];
    __shared__ float spk[64];
    int tid = threadIdx.x;
    if (tid < 64) {
        float acc = b1[tid];
        for (int k = 0; k < 28; k++) acc += pf[k] * W1[k * 64 + tid];
        t1[tid] = fmaxf(acc, 0.f);
    }
    __syncthreads();
    if (tid < 64) {
        float acc = b2[tid];
        for (int jj = 0; jj < 64; jj++) acc += t1[jj] * W2[jj * 64 + tid];
        spk[tid] = acc;
    }
    __syncthreads();
    for (int idx = tid; idx < 64 * HH; idx += blockDim.x) {
        int o = idx / HH, i2 = idx % HH;
        const float* wrow = bilW + ((long long)o * HH + i2) * 64;
        float acc = 0.f;
        #pragma unroll 8
        for (int jj = 0; jj < 64; jj++) acc += wrow[jj] * spk[jj];
        g_Wp[o * HH + i2] = acc;
    }
}

// ---------------- pool (binary search, no atomics) + bilinear + classifier ----
__global__ void k_pool_final(const void* __restrict__ batch,
                             const float* __restrict__ bil_b,
                             const float* __restrict__ cW1, const float* __restrict__ cb1,
                             const float* __restrict__ cW2, const float* __restrict__ cb2,
                             float* __restrict__ out) {
    __shared__ int   sLo, sHi;
    __shared__ float lig[HH];
    __shared__ float inter[64];
    __shared__ float c1[32];
    int g = blockIdx.x;
    int tid = threadIdx.x;
    int is64 = g_is64;
    if (tid < 2) {
        int key = g + tid;            // lower_bound(batch, key)
        int lo = 0, hi = NN;
        while (lo < hi) {
            int mid = (lo + hi) >> 1;
            if (load_idx(batch, mid, is64) < key) lo = mid + 1; else hi = mid;
        }
        if (tid == 0) sLo = lo; else sHi = lo;
    }
    __syncthreads();
    int lo = sLo, hi = sHi;
    float s0 = 0.f, s1 = 0.f;
    for (int r = lo; r < hi; r++) {
        s0 += g_h[r * HH + tid];
        s1 += g_h[r * HH + tid + 64];   // 128 threads? -> blockDim 64
    }
    // blockDim.x == 64: each thread covers feature tid and tid+64
    float cnt = fmaxf((float)(hi - lo), 1.f);
    lig[tid]      = s0 / cnt;
    lig[tid + 64] = s1 / cnt;
    __syncthreads();
    {
        float acc = bil_b[tid];
        const float* wp = &g_Wp[tid * HH];
        #pragma unroll 8
        for (int i = 0; i < HH; i++) acc += lig[i] * wp[i];
        inter[tid] = acc;
    }
    __syncthreads();
    if (tid < 32) {
        float acc = cb1[tid];
        #pragma unroll 8
        for (int o = 0; o < 64; o++) acc += inter[o] * cW1[o * 32 + tid];
        c1[tid] = fmaxf(acc, 0.f);
    }
    __syncthreads();
    if (tid == 0) {
        float acc = cb2[0];
        #pragma unroll
        for (int t = 0; t < 32; t++) acc += c1[t] * cW2[t];
        out[g] = acc;
    }
}

// ---------------- launch --------------------------------------------------------
extern "C" void kernel_launch(void* const* d_in, const int* in_sizes, int n_in,
                              void* d_out, int out_size) {
    const float* x       = (const float*)d_in[0];
    const void*  ei      = d_in[1];
    const void*  batch   = d_in[2];
    const float* pocket  = (const float*)d_in[3];
    const float* conv0_W = (const float*)d_in[4];
    const float* conv0_b = (const float*)d_in[5];
    const float* convs_W = (const float*)d_in[6];
    const float* convs_b = (const float*)d_in[7];
    const float* bn_g    = (const float*)d_in[8];
    const float* bn_b    = (const float*)d_in[9];
    const float* bn_m    = (const float*)d_in[10];
    const float* bn_v    = (const float*)d_in[11];
    const float* pW1     = (const float*)d_in[12];
    const float* pb1     = (const float*)d_in[13];
    const float* pW2     = (const float*)d_in[14];
    const float* pb2     = (const float*)d_in[15];
    const float* bilW    = (const float*)d_in[16];
    const float* bilb    = (const float*)d_in[17];
    const float* cW1     = (const float*)d_in[18];
    const float* cb1     = (const float*)d_in[19];
    const float* cW2     = (const float*)d_in[20];
    const float* cb2     = (const float*)d_in[21];
    float* out = (float*)d_out;

    float* h  = nullptr; float* hw = nullptr;
    cudaGetSymbolAddress((void**)&h,  g_h);
    cudaGetSymbolAddress((void**)&hw, g_hw);

    const int TB = 256;
    // CSR build
    k_detect<<<1, 32>>>(ei);
    k_small<<<1, 128>>>(pocket, pW1, pb1, pW2, pb2, bilW);   // independent, early
    k_zero_deg<<<(NN + TB - 1) / TB, TB>>>();
    k_deg_count<<<(NE + TB - 1) / TB, TB>>>(ei);
    k_scanA<<<NB, 1024>>>();
    k_scanB<<<1, 32>>>();
    k_scanC<<<NB, 1024>>>();
    k_scatter<<<(NE + TB - 1) / TB, TB>>>(ei);

    int agg_blocks = (NN * 32 + TB - 1) / TB;

    // layer 0
    k_gemm0<<<(NN + 7) / 8, HH>>>(x, conv0_W);
    k_agg<<<agg_blocks, TB>>>(hw, h, conv0_b,
                              bn_g + 0 * HH, bn_b + 0 * HH, bn_m + 0 * HH, bn_v + 0 * HH);
    // layers 1,2
    for (int l = 1; l <= 2; l++) {
        const float* W = convs_W + (long long)(l - 1) * HH * HH;
        const float* b = convs_b + (l - 1) * HH;
        k_gemm128<<<(NN + 63) / 64, 256>>>(h, W, hw);
        k_agg<<<agg_blocks, TB>>>(hw, h, b,
                                  bn_g + l * HH, bn_b + l * HH, bn_m + l * HH, bn_v + l * HH);
    }

    // pool + bilinear + classifier (one block per graph, 64 threads)
    k_pool_final<<<GG, 64>>>(batch, bilb, cW1, cb1, cW2, cb2, out);
}

// round 4
// speedup vs baseline: 1.7575x; 1.4845x over previous
#include <cuda_runtime.h>
#include <cuda_fp16.h>

#define NN 50000
#define NE 1600000
#define HH 128
#define GG 256
#define BN_EPS 1e-5f
#define NB ((NN + 1023) / 1024)   // 49 scan blocks

// ---------------- scratch (static device memory) ----------------------------
__device__ int    g_is64;
__device__ int    g_deg[NN];
__device__ int    g_rowoff[NN + 1];
__device__ int    g_cursor[NN];
__device__ int2   g_edge[NE];          // {src, coef bits}
__device__ float  g_dinv[NN];
__device__ int    g_bsum[NB];
__device__ int    g_boff[NB];
__device__ float  g_h[NN * HH];
__device__ float  g_hw[NN * HH];
__device__ __half g_hw16[NN * HH];
__device__ float  g_Wp[64 * HH];

__device__ __forceinline__ int load_idx(const void* p, long long i, int is64) {
    if (is64) return (int)((const long long*)p)[i];
    return ((const int*)p)[i];
}

__device__ __forceinline__ int h2i(__half2 h) {
    return *reinterpret_cast<int*>(&h);
}

// ---------------- dtype detection (parallel, 1 warp) -------------------------
__global__ void k_detect(const void* ei) {
    const int* p = (const int*)ei;
    int lane = threadIdx.x;
    int nz = 0;
    #pragma unroll
    for (int r = 0; r < 4; r++) {
        if (p[(lane + r * 32) * 2 + 1] != 0) nz = 1;
    }
    unsigned m = __ballot_sync(0xFFFFFFFFu, nz);
    if (lane == 0) g_is64 = (m == 0u) ? 1 : 0;
}

// ---------------- degree / CSR build -----------------------------------------
// 2 edges per thread, vector loads
__global__ void k_deg_count(const void* ei) {
    int t = blockIdx.x * blockDim.x + threadIdx.x;
    if (t >= NE / 2) return;
    int d0, d1;
    if (g_is64) {
        int4 v = __ldg((const int4*)((const long long*)ei + NE) + t);
        d0 = v.x; d1 = v.z;
    } else {
        int2 v = __ldg((const int2*)((const int*)ei + NE) + t);
        d0 = v.x; d1 = v.y;
    }
    atomicAdd(&g_deg[d0], 1);
    atomicAdd(&g_deg[d1], 1);
}

// per-block (1024) scan; writes local exclusive prefix + block sums + dinv
__global__ void k_scanA() {
    int i = blockIdx.x * 1024 + threadIdx.x;
    int v = (i < NN) ? g_deg[i] : 0;
    int lane = threadIdx.x & 31, wid = threadIdx.x >> 5;
    int s = v;
    #pragma unroll
    for (int o = 1; o < 32; o <<= 1) {
        int t = __shfl_up_sync(0xFFFFFFFFu, s, o);
        if (lane >= o) s += t;
    }
    __shared__ int wsum[32];
    if (lane == 31) wsum[wid] = s;
    __syncthreads();
    if (wid == 0) {
        int t = wsum[lane];
        #pragma unroll
        for (int o = 1; o < 32; o <<= 1) {
            int u = __shfl_up_sync(0xFFFFFFFFu, t, o);
            if (lane >= o) t += u;
        }
        wsum[lane] = t;
    }
    __syncthreads();
    int incl = s + (wid > 0 ? wsum[wid - 1] : 0);
    if (i < NN) {
        g_rowoff[i] = incl - v;
        g_dinv[i]   = rsqrtf((float)v + 1.0f);
    }
    if (threadIdx.x == 1023) g_bsum[blockIdx.x] = incl;
}

// warp scan over the 49 block sums
__global__ void k_scanB() {
    int lane = threadIdx.x;
    int carry = 0;
    for (int base = 0; base < NB; base += 32) {
        int idx = base + lane;
        int v = (idx < NB) ? g_bsum[idx] : 0;
        int s = v;
        #pragma unroll
        for (int o = 1; o < 32; o <<= 1) {
            int t = __shfl_up_sync(0xFFFFFFFFu, s, o);
            if (lane >= o) s += t;
        }
        if (idx < NB) g_boff[idx] = carry + s - v;
        carry += __shfl_sync(0xFFFFFFFFu, s, 31);
    }
    if (lane == 0) g_rowoff[NN] = carry;
}

__global__ void k_scanC() {
    int i = blockIdx.x * 1024 + threadIdx.x;
    if (i < NN) {
        int v = g_rowoff[i] + g_boff[blockIdx.x];
        g_rowoff[i] = v;
        g_cursor[i] = v;
    }
}

// 2 edges per thread
__global__ void k_scatter(const void* ei) {
    int t = blockIdx.x * blockDim.x + threadIdx.x;
    if (t >= NE / 2) return;
    int s0, s1, d0, d1;
    if (g_is64) {
        int4 sv = __ldg((const int4*)((const long long*)ei) + t);
        int4 dv = __ldg((const int4*)((const long long*)ei + NE) + t);
        s0 = sv.x; s1 = sv.z; d0 = dv.x; d1 = dv.z;
    } else {
        int2 sv = __ldg((const int2*)((const int*)ei) + t);
        int2 dv = __ldg((const int2*)((const int*)ei + NE) + t);
        s0 = sv.x; s1 = sv.y; d0 = dv.x; d1 = dv.y;
    }
    float c0 = g_dinv[s0] * g_dinv[d0];
    float c1 = g_dinv[s1] * g_dinv[d1];
    int p0 = atomicAdd(&g_cursor[d0], 1);
    g_edge[p0] = make_int2(s0, __float_as_int(c0));
    int p1 = atomicAdd(&g_cursor[d1], 1);
    g_edge[p1] = make_int2(s1, __float_as_int(c1));
}

// ---------------- GEMMs -------------------------------------------------------
// layer 0: hw = x[N,7] @ W0[7,128]; 8 rows per block; dual fp32/fp16 write
__global__ void k_gemm0(const float* __restrict__ x, const float* __restrict__ W) {
    __shared__ float sx[8][7];
    int row0 = blockIdx.x * 8;
    int tid = threadIdx.x;
    if (tid < 56) {
        int r = tid / 7, c = tid % 7;
        int gr = row0 + r;
        sx[r][c] = (gr < NN) ? x[gr * 7 + c] : 0.f;
    }
    __syncthreads();
    #pragma unroll
    for (int r = 0; r < 8; r++) {
        int gr = row0 + r;
        if (gr < NN) {
            float acc = 0.f;
            #pragma unroll
            for (int k = 0; k < 7; k++) acc += sx[r][k] * W[k * HH + tid];
            g_hw[gr * HH + tid] = acc;
            g_hw16[gr * HH + tid] = __float2half_rn(acc);
        }
    }
}

// C = A[N,128] @ W[128,128]; 64 rows/block, 128 threads, 8x8 register tile
__global__ void __launch_bounds__(128) k_gemm(const float* __restrict__ A,
                                              const float* __restrict__ W,
                                              float* __restrict__ C,
                                              __half* __restrict__ C16) {
    __shared__ float sA[64][HH];
    int row0 = blockIdx.x * 64;
    int tid = threadIdx.x;
    // stage A: 64x128 floats = 2048 float4, 16 per thread, coalesced
    for (int i = tid; i < 64 * 32; i += 128) {
        int r = i >> 5, c4 = i & 31;
        int gr = row0 + r;
        float4 v = (gr < NN) ? *(const float4*)&A[gr * HH + c4 * 4]
                             : make_float4(0.f, 0.f, 0.f, 0.f);
        *(float4*)&sA[r][c4 * 4] = v;
    }
    __syncthreads();
    int cg = tid & 15;       // 16 col groups of 8
    int rg = tid >> 4;       // 8 row groups of 8
    float acc[8][8] = {};
    #pragma unroll 2
    for (int k = 0; k < HH; k++) {
        float4 w0 = __ldg((const float4*)&W[k * HH + cg * 8]);
        float4 w1 = __ldg((const float4*)&W[k * HH + cg * 8 + 4]);
        #pragma unroll
        for (int r = 0; r < 8; r++) {
            float a = sA[rg * 8 + r][k];
            acc[r][0] += a * w0.x; acc[r][1] += a * w0.y;
            acc[r][2] += a * w0.z; acc[r][3] += a * w0.w;
            acc[r][4] += a * w1.x; acc[r][5] += a * w1.y;
            acc[r][6] += a * w1.z; acc[r][7] += a * w1.w;
        }
    }
    #pragma unroll
    for (int r = 0; r < 8; r++) {
        int gr = row0 + rg * 8 + r;
        if (gr < NN) {
            float* cp = &C[gr * HH + cg * 8];
            *(float4*)cp       = make_float4(acc[r][0], acc[r][1], acc[r][2], acc[r][3]);
            *(float4*)(cp + 4) = make_float4(acc[r][4], acc[r][5], acc[r][6], acc[r][7]);
            __half2 h0 = __floats2half2_rn(acc[r][0], acc[r][1]);
            __half2 h1 = __floats2half2_rn(acc[r][2], acc[r][3]);
            __half2 h2 = __floats2half2_rn(acc[r][4], acc[r][5]);
            __half2 h3 = __floats2half2_rn(acc[r][6], acc[r][7]);
            int4 pk = make_int4(h2i(h0), h2i(h1), h2i(h2), h2i(h3));
            *(int4*)&C16[gr * HH + cg * 8] = pk;
        }
    }
}

// ---------------- fused aggregation + bias + BN + ReLU ------------------------
// warp per node; lane = 4 features; neighbors from fp16 copy, self from fp32
__global__ void k_agg(const float* __restrict__ hw, const __half* __restrict__ hw16,
                      float* __restrict__ hout,
                      const float* __restrict__ bias,
                      const float* __restrict__ gamma, const float* __restrict__ beta,
                      const float* __restrict__ mean,  const float* __restrict__ var) {
    int v = (blockIdx.x * blockDim.x + threadIdx.x) >> 5;
    int lane = threadIdx.x & 31;
    if (v >= NN) return;
    float di = g_dinv[v];
    float c0 = di * di;
    int j = lane * 4;
    float4 a = *(const float4*)&hw[v * HH + j];
    float ax = c0 * a.x, ay = c0 * a.y, az = c0 * a.z, aw = c0 * a.w;
    int e0 = g_rowoff[v], e1 = g_rowoff[v + 1];
    for (int e = e0; e < e1; e++) {
        int2 ed = __ldg(&g_edge[e]);               // warp-broadcast
        float c = __int_as_float(ed.y);
        uint2 u = __ldg((const uint2*)(hw16 + ed.x * HH + j));
        float2 f0 = __half22float2(*(const __half2*)&u.x);
        float2 f1 = __half22float2(*(const __half2*)&u.y);
        ax += c * f0.x; ay += c * f0.y; az += c * f1.x; aw += c * f1.y;
    }
    float4 b4 = *(const float4*)&bias[j];
    float4 g4 = *(const float4*)&gamma[j];
    float4 be4 = *(const float4*)&beta[j];
    float4 m4 = *(const float4*)&mean[j];
    float4 v4 = *(const float4*)&var[j];
    float4 o;
    o.x = fmaxf(g4.x * (ax + b4.x - m4.x) * rsqrtf(v4.x + BN_EPS) + be4.x, 0.f);
    o.y = fmaxf(g4.y * (ay + b4.y - m4.y) * rsqrtf(v4.y + BN_EPS) + be4.y, 0.f);
    o.z = fmaxf(g4.z * (az + b4.z - m4.z) * rsqrtf(v4.z + BN_EPS) + be4.z, 0.f);
    o.w = fmaxf(g4.w * (aw + b4.w - m4.w) * rsqrtf(v4.w + BN_EPS) + be4.w, 0.f);
    *(float4*)&hout[v * HH + j] = o;
}

// ---------------- pocket MLP + bilinear weight contraction --------------------
__global__ void k_small(const float* __restrict__ pf,
                        const float* __restrict__ W1, const float* __restrict__ b1,
                        const float* __restrict__ W2, const float* __restrict__ b2,
                        const float* __restrict__ bilW) {
    __shared__ float t1[64];
    __shared__ float spk[64];
    int tid = threadIdx.x;
    if (tid < 64) {
        float acc = b1[tid];
        for (int k = 0; k < 28; k++) acc += pf[k] * W1[k * 64 + tid];
        t1[tid] = fmaxf(acc, 0.f);
    }
    __syncthreads();
    if (tid < 64) {
        float acc = b2[tid];
        for (int jj = 0; jj < 64; jj++) acc += t1[jj] * W2[jj * 64 + tid];
        spk[tid] = acc;
    }
    __syncthreads();
    for (int idx = tid; idx < 64 * HH; idx += blockDim.x) {
        int o = idx / HH, i2 = idx % HH;
        const float4* wrow = (const float4*)(bilW + ((long long)o * HH + i2) * 64);
        float acc = 0.f;
        #pragma unroll
        for (int jj = 0; jj < 16; jj++) {
            float4 w = __ldg(&wrow[jj]);
            const float4 s = *(const float4*)&spk[jj * 4];
            acc += w.x * s.x + w.y * s.y + w.z * s.z + w.w * s.w;
        }
        g_Wp[o * HH + i2] = acc;
    }
}

// ---------------- pool (binary search) + bilinear + classifier ----------------
__global__ void k_pool_final(const void* __restrict__ batch,
                             const float* __restrict__ bil_b,
                             const float* __restrict__ cW1, const float* __restrict__ cb1,
                             const float* __restrict__ cW2, const float* __restrict__ cb2,
                             float* __restrict__ out) {
    __shared__ int   sLo, sHi;
    __shared__ float lig[HH];
    __shared__ float inter[64];
    __shared__ float c1[32];
    int g = blockIdx.x;
    int tid = threadIdx.x;
    int is64 = g_is64;
    if (tid < 2) {
        int key = g + tid;            // lower_bound(batch, key)
        int lo = 0, hi = NN;
        while (lo < hi) {
            int mid = (lo + hi) >> 1;
            if (load_idx(batch, mid, is64) < key) lo = mid + 1; else hi = mid;
        }
        if (tid == 0) sLo = lo; else sHi = lo;
    }
    __syncthreads();
    int lo = sLo, hi = sHi;
    float s0 = 0.f, s1 = 0.f;
    for (int r = lo; r < hi; r++) {
        s0 += g_h[r * HH + tid];
        s1 += g_h[r * HH + tid + 64];
    }
    float cnt = fmaxf((float)(hi - lo), 1.f);
    lig[tid]      = s0 / cnt;
    lig[tid + 64] = s1 / cnt;
    __syncthreads();
    {
        float acc = bil_b[tid];
        const float* wp = &g_Wp[tid * HH];
        #pragma unroll 8
        for (int i = 0; i < HH; i++) acc += lig[i] * wp[i];
        inter[tid] = acc;
    }
    __syncthreads();
    if (tid < 32) {
        float acc = cb1[tid];
        #pragma unroll 8
        for (int o = 0; o < 64; o++) acc += inter[o] * cW1[o * 32 + tid];
        c1[tid] = fmaxf(acc, 0.f);
    }
    __syncthreads();
    if (tid == 0) {
        float acc = cb2[0];
        #pragma unroll
        for (int t = 0; t < 32; t++) acc += c1[t] * cW2[t];
        out[g] = acc;
    }
}

// ---------------- launch --------------------------------------------------------
extern "C" void kernel_launch(void* const* d_in, const int* in_sizes, int n_in,
                              void* d_out, int out_size) {
    const float* x       = (const float*)d_in[0];
    const void*  ei      = d_in[1];
    const void*  batch   = d_in[2];
    const float* pocket  = (const float*)d_in[3];
    const float* conv0_W = (const float*)d_in[4];
    const float* conv0_b = (const float*)d_in[5];
    const float* convs_W = (const float*)d_in[6];
    const float* convs_b = (const float*)d_in[7];
    const float* bn_g    = (const float*)d_in[8];
    const float* bn_b    = (const float*)d_in[9];
    const float* bn_m    = (const float*)d_in[10];
    const float* bn_v    = (const float*)d_in[11];
    const float* pW1     = (const float*)d_in[12];
    const float* pb1     = (const float*)d_in[13];
    const float* pW2     = (const float*)d_in[14];
    const float* pb2     = (const float*)d_in[15];
    const float* bilW    = (const float*)d_in[16];
    const float* bilb    = (const float*)d_in[17];
    const float* cW1     = (const float*)d_in[18];
    const float* cb1     = (const float*)d_in[19];
    const float* cW2     = (const float*)d_in[20];
    const float* cb2     = (const float*)d_in[21];
    float* out = (float*)d_out;

    float* h = nullptr; float* hw = nullptr; __half* hw16 = nullptr; int* degp = nullptr;
    cudaGetSymbolAddress((void**)&h,    g_h);
    cudaGetSymbolAddress((void**)&hw,   g_hw);
    cudaGetSymbolAddress((void**)&hw16, g_hw16);
    cudaGetSymbolAddress((void**)&degp, g_deg);

    const int TB = 256;
    // CSR build
    k_detect<<<1, 32>>>(ei);
    k_small<<<1, 256>>>(pocket, pW1, pb1, pW2, pb2, bilW);   // independent, early
    cudaMemsetAsync(degp, 0, NN * sizeof(int));
    k_deg_count<<<(NE / 2 + TB - 1) / TB, TB>>>(ei);
    k_scanA<<<NB, 1024>>>();
    k_scanB<<<1, 32>>>();
    k_scanC<<<NB, 1024>>>();
    k_scatter<<<(NE / 2 + TB - 1) / TB, TB>>>(ei);

    int agg_blocks = (NN * 32 + TB - 1) / TB;

    // layer 0
    k_gemm0<<<(NN + 7) / 8, HH>>>(x, conv0_W);
    k_agg<<<agg_blocks, TB>>>(hw, hw16, h, conv0_b,
                              bn_g + 0 * HH, bn_b + 0 * HH, bn_m + 0 * HH, bn_v + 0 * HH);
    // layers 1,2
    for (int l = 1; l <= 2; l++) {
        const float* W = convs_W + (long long)(l - 1) * HH * HH;
        const float* b = convs_b + (l - 1) * HH;
        k_gemm<<<(NN + 63) / 64, 128>>>(h, W, hw, hw16);
        k_agg<<<agg_blocks, TB>>>(hw, hw16, h, b,
                                  bn_g + l * HH, bn_b + l * HH, bn_m + l * HH, bn_v + l * HH);
    }

    // pool + bilinear + classifier (one block per graph, 64 threads)
    k_pool_final<<<GG, 64>>>(batch, bilb, cW1, cb1, cW2, cb2, out);
}

// round 5
// speedup vs baseline: 2.0942x; 1.1916x over previous
#include <cuda_runtime.h>
#include <cuda_fp16.h>

#define NN 50000
#define NE 1600000
#define HH 128
#define GG 256
#define BN_EPS 1e-5f
#define NB ((NN + 1023) / 1024)   // 49 scan blocks

// ---------------- scratch (static device memory) ----------------------------
__device__ int    g_is64;
__device__ int    g_deg[NN];
__device__ int    g_rowoff[NN + 1];
__device__ int    g_cursor[NN];
__device__ int2   g_edge[NE];          // {src, coef bits}
__device__ float  g_dinv[NN];
__device__ int    g_bsum[NB];
__device__ int    g_boff[NB];
__device__ float  g_h[NN * HH];
__device__ __half g_hw16[NN * HH];
__device__ float  g_Wp[64 * HH];

__device__ __forceinline__ int load_idx(const void* p, long long i, int is64) {
    if (is64) return (int)((const long long*)p)[i];
    return ((const int*)p)[i];
}

__device__ __forceinline__ int h2i(__half2 h) {
    return *reinterpret_cast<int*>(&h);
}

// ---------------- dtype detection (parallel, 1 warp) -------------------------
__global__ void k_detect(const void* ei) {
    const int* p = (const int*)ei;
    int lane = threadIdx.x;
    int nz = 0;
    #pragma unroll
    for (int r = 0; r < 4; r++) {
        if (p[(lane + r * 32) * 2 + 1] != 0) nz = 1;
    }
    unsigned m = __ballot_sync(0xFFFFFFFFu, nz);
    if (lane == 0) g_is64 = (m == 0u) ? 1 : 0;
}

// ---------------- degree / CSR build -----------------------------------------
__global__ void k_deg_count(const void* ei) {
    int t = blockIdx.x * blockDim.x + threadIdx.x;
    if (t >= NE / 2) return;
    int d0, d1;
    if (g_is64) {
        int4 v = __ldg((const int4*)((const long long*)ei + NE) + t);
        d0 = v.x; d1 = v.z;
    } else {
        int2 v = __ldg((const int2*)((const int*)ei + NE) + t);
        d0 = v.x; d1 = v.y;
    }
    atomicAdd(&g_deg[d0], 1);
    atomicAdd(&g_deg[d1], 1);
}

__global__ void k_scanA() {
    int i = blockIdx.x * 1024 + threadIdx.x;
    int v = (i < NN) ? g_deg[i] : 0;
    int lane = threadIdx.x & 31, wid = threadIdx.x >> 5;
    int s = v;
    #pragma unroll
    for (int o = 1; o < 32; o <<= 1) {
        int t = __shfl_up_sync(0xFFFFFFFFu, s, o);
        if (lane >= o) s += t;
    }
    __shared__ int wsum[32];
    if (lane == 31) wsum[wid] = s;
    __syncthreads();
    if (wid == 0) {
        int t = wsum[lane];
        #pragma unroll
        for (int o = 1; o < 32; o <<= 1) {
            int u = __shfl_up_sync(0xFFFFFFFFu, t, o);
            if (lane >= o) t += u;
        }
        wsum[lane] = t;
    }
    __syncthreads();
    int incl = s + (wid > 0 ? wsum[wid - 1] : 0);
    if (i < NN) {
        g_rowoff[i] = incl - v;
        g_dinv[i]   = rsqrtf((float)v + 1.0f);
    }
    if (threadIdx.x == 1023) g_bsum[blockIdx.x] = incl;
}

__global__ void k_scanB() {
    int lane = threadIdx.x;
    int carry = 0;
    for (int base = 0; base < NB; base += 32) {
        int idx = base + lane;
        int v = (idx < NB) ? g_bsum[idx] : 0;
        int s = v;
        #pragma unroll
        for (int o = 1; o < 32; o <<= 1) {
            int t = __shfl_up_sync(0xFFFFFFFFu, s, o);
            if (lane >= o) s += t;
        }
        if (idx < NB) g_boff[idx] = carry + s - v;
        carry += __shfl_sync(0xFFFFFFFFu, s, 31);
    }
    if (lane == 0) g_rowoff[NN] = carry;
}

__global__ void k_scanC() {
    int i = blockIdx.x * 1024 + threadIdx.x;
    if (i < NN) {
        int v = g_rowoff[i] + g_boff[blockIdx.x];
        g_rowoff[i] = v;
        g_cursor[i] = v;
    }
}

__global__ void k_scatter(const void* ei) {
    int t = blockIdx.x * blockDim.x + threadIdx.x;
    if (t >= NE / 2) return;
    int s0, s1, d0, d1;
    if (g_is64) {
        int4 sv = __ldg((const int4*)((const long long*)ei) + t);
        int4 dv = __ldg((const int4*)((const long long*)ei + NE) + t);
        s0 = sv.x; s1 = sv.z; d0 = dv.x; d1 = dv.z;
    } else {
        int2 sv = __ldg((const int2*)((const int*)ei) + t);
        int2 dv = __ldg((const int2*)((const int*)ei + NE) + t);
        s0 = sv.x; s1 = sv.y; d0 = dv.x; d1 = dv.y;
    }
    float c0 = g_dinv[s0] * g_dinv[d0];
    float c1 = g_dinv[s1] * g_dinv[d1];
    int p0 = atomicAdd(&g_cursor[d0], 1);
    g_edge[p0] = make_int2(s0, __float_as_int(c0));
    int p1 = atomicAdd(&g_cursor[d1], 1);
    g_edge[p1] = make_int2(s1, __float_as_int(c1));
}

// ---------------- GEMMs -------------------------------------------------------
// layer 0: hw16 = fp16(x[N,7] @ W0[7,128]); 8 rows per block
__global__ void k_gemm0(const float* __restrict__ x, const float* __restrict__ W) {
    __shared__ float sx[8][7];
    int row0 = blockIdx.x * 8;
    int tid = threadIdx.x;
    if (tid < 56) {
        int r = tid / 7, c = tid % 7;
        int gr = row0 + r;
        sx[r][c] = (gr < NN) ? x[gr * 7 + c] : 0.f;
    }
    __syncthreads();
    #pragma unroll
    for (int r = 0; r < 8; r++) {
        int gr = row0 + r;
        if (gr < NN) {
            float acc = 0.f;
            #pragma unroll
            for (int k = 0; k < 7; k++) acc += sx[r][k] * W[k * HH + tid];
            g_hw16[gr * HH + tid] = __float2half_rn(acc);
        }
    }
}

// C16 = fp16(A[N,128] @ W[128,128]); 64 rows/block, 128 threads, 8x8 tile,
// k-loop grouped by 4 with float4 LDS
__global__ void __launch_bounds__(128) k_gemm(const float* __restrict__ A,
                                              const float* __restrict__ W,
                                              __half* __restrict__ C16) {
    __shared__ float sA[64][HH];
    int row0 = blockIdx.x * 64;
    int tid = threadIdx.x;
    for (int i = tid; i < 64 * 32; i += 128) {
        int r = i >> 5, c4 = i & 31;
        int gr = row0 + r;
        float4 v = (gr < NN) ? *(const float4*)&A[gr * HH + c4 * 4]
                             : make_float4(0.f, 0.f, 0.f, 0.f);
        *(float4*)&sA[r][c4 * 4] = v;
    }
    __syncthreads();
    int cg = tid & 15;       // 16 col groups of 8
    int rg = tid >> 4;       // 8 row groups of 8
    float acc[8][8] = {};
    for (int k0 = 0; k0 < HH; k0 += 4) {
        float4 wv[4][2];
        #pragma unroll
        for (int kk = 0; kk < 4; kk++) {
            wv[kk][0] = __ldg((const float4*)&W[(k0 + kk) * HH + cg * 8]);
            wv[kk][1] = __ldg((const float4*)&W[(k0 + kk) * HH + cg * 8 + 4]);
        }
        #pragma unroll
        for (int r = 0; r < 8; r++) {
            float4 a = *(const float4*)&sA[rg * 8 + r][k0];
            acc[r][0] += a.x * wv[0][0].x; acc[r][1] += a.x * wv[0][0].y;
            acc[r][2] += a.x * wv[0][0].z; acc[r][3] += a.x * wv[0][0].w;
            acc[r][4] += a.x * wv[0][1].x; acc[r][5] += a.x * wv[0][1].y;
            acc[r][6] += a.x * wv[0][1].z; acc[r][7] += a.x * wv[0][1].w;

            acc[r][0] += a.y * wv[1][0].x; acc[r][1] += a.y * wv[1][0].y;
            acc[r][2] += a.y * wv[1][0].z; acc[r][3] += a.y * wv[1][0].w;
            acc[r][4] += a.y * wv[1][1].x; acc[r][5] += a.y * wv[1][1].y;
            acc[r][6] += a.y * wv[1][1].z; acc[r][7] += a.y * wv[1][1].w;

            acc[r][0] += a.z * wv[2][0].x; acc[r][1] += a.z * wv[2][0].y;
            acc[r][2] += a.z * wv[2][0].z; acc[r][3] += a.z * wv[2][0].w;
            acc[r][4] += a.z * wv[2][1].x; acc[r][5] += a.z * wv[2][1].y;
            acc[r][6] += a.z * wv[2][1].z; acc[r][7] += a.z * wv[2][1].w;

            acc[r][0] += a.w * wv[3][0].x; acc[r][1] += a.w * wv[3][0].y;
            acc[r][2] += a.w * wv[3][0].z; acc[r][3] += a.w * wv[3][0].w;
            acc[r][4] += a.w * wv[3][1].x; acc[r][5] += a.w * wv[3][1].y;
            acc[r][6] += a.w * wv[3][1].z; acc[r][7] += a.w * wv[3][1].w;
        }
    }
    #pragma unroll
    for (int r = 0; r < 8; r++) {
        int gr = row0 + rg * 8 + r;
        if (gr < NN) {
            __half2 h0 = __floats2half2_rn(acc[r][0], acc[r][1]);
            __half2 h1 = __floats2half2_rn(acc[r][2], acc[r][3]);
            __half2 h2 = __floats2half2_rn(acc[r][4], acc[r][5]);
            __half2 h3 = __floats2half2_rn(acc[r][6], acc[r][7]);
            int4 pk = make_int4(h2i(h0), h2i(h1), h2i(h2), h2i(h3));
            *(int4*)&C16[gr * HH + cg * 8] = pk;
        }
    }
}

// ---------------- fused aggregation + bias + BN + ReLU ------------------------
// warp per node; lane = 4 features; all rows fp16; edge loop unrolled x4 (MLP)
__global__ void k_agg(const __half* __restrict__ hw16,
                      float* __restrict__ hout,
                      const float* __restrict__ bias,
                      const float* __restrict__ gamma, const float* __restrict__ beta,
                      const float* __restrict__ mean,  const float* __restrict__ var) {
    int v = (blockIdx.x * blockDim.x + threadIdx.x) >> 5;
    int lane = threadIdx.x & 31;
    if (v >= NN) return;
    float di = g_dinv[v];
    float c0 = di * di;
    int j = lane * 4;
    uint2 us = __ldg((const uint2*)(hw16 + (long long)v * HH + j));
    float2 s0 = __half22float2(*(const __half2*)&us.x);
    float2 s1 = __half22float2(*(const __half2*)&us.y);
    float ax = c0 * s0.x, ay = c0 * s0.y, az = c0 * s1.x, aw = c0 * s1.y;
    int e0 = g_rowoff[v], e1 = g_rowoff[v + 1];
    int e = e0;
    for (; e + 3 < e1; e += 4) {
        int2 eA = __ldg(&g_edge[e + 0]);
        int2 eB = __ldg(&g_edge[e + 1]);
        int2 eC = __ldg(&g_edge[e + 2]);
        int2 eD = __ldg(&g_edge[e + 3]);
        uint2 uA = __ldg((const uint2*)(hw16 + (long long)eA.x * HH + j));
        uint2 uB = __ldg((const uint2*)(hw16 + (long long)eB.x * HH + j));
        uint2 uC = __ldg((const uint2*)(hw16 + (long long)eC.x * HH + j));
        uint2 uD = __ldg((const uint2*)(hw16 + (long long)eD.x * HH + j));
        float cA = __int_as_float(eA.y), cB = __int_as_float(eB.y);
        float cC = __int_as_float(eC.y), cD = __int_as_float(eD.y);
        float2 a0 = __half22float2(*(const __half2*)&uA.x);
        float2 a1 = __half22float2(*(const __half2*)&uA.y);
        ax += cA * a0.x; ay += cA * a0.y; az += cA * a1.x; aw += cA * a1.y;
        float2 b0 = __half22float2(*(const __half2*)&uB.x);
        float2 b1 = __half22float2(*(const __half2*)&uB.y);
        ax += cB * b0.x; ay += cB * b0.y; az += cB * b1.x; aw += cB * b1.y;
        float2 c0v = __half22float2(*(const __half2*)&uC.x);
        float2 c1v = __half22float2(*(const __half2*)&uC.y);
        ax += cC * c0v.x; ay += cC * c0v.y; az += cC * c1v.x; aw += cC * c1v.y;
        float2 d0 = __half22float2(*(const __half2*)&uD.x);
        float2 d1 = __half22float2(*(const __half2*)&uD.y);
        ax += cD * d0.x; ay += cD * d0.y; az += cD * d1.x; aw += cD * d1.y;
    }
    for (; e < e1; e++) {
        int2 ed = __ldg(&g_edge[e]);
        float c = __int_as_float(ed.y);
        uint2 u = __ldg((const uint2*)(hw16 + (long long)ed.x * HH + j));
        float2 f0 = __half22float2(*(const __half2*)&u.x);
        float2 f1 = __half22float2(*(const __half2*)&u.y);
        ax += c * f0.x; ay += c * f0.y; az += c * f1.x; aw += c * f1.y;
    }
    float4 b4 = *(const float4*)&bias[j];
    float4 g4 = *(const float4*)&gamma[j];
    float4 be4 = *(const float4*)&beta[j];
    float4 m4 = *(const float4*)&mean[j];
    float4 v4 = *(const float4*)&var[j];
    float4 o;
    o.x = fmaxf(g4.x * (ax + b4.x - m4.x) * rsqrtf(v4.x + BN_EPS) + be4.x, 0.f);
    o.y = fmaxf(g4.y * (ay + b4.y - m4.y) * rsqrtf(v4.y + BN_EPS) + be4.y, 0.f);
    o.z = fmaxf(g4.z * (az + b4.z - m4.z) * rsqrtf(v4.z + BN_EPS) + be4.z, 0.f);
    o.w = fmaxf(g4.w * (aw + b4.w - m4.w) * rsqrtf(v4.w + BN_EPS) + be4.w, 0.f);
    *(float4*)&hout[(long long)v * HH + j] = o;
}

// ---------------- pocket MLP + bilinear weight contraction --------------------
__global__ void k_small(const float* __restrict__ pf,
                        const float* __restrict__ W1, const float* __restrict__ b1,
                        const float* __restrict__ W2, const float* __restrict__ b2,
                        const float* __restrict__ bilW) {
    __shared__ float t1[64];
    __shared__ float spk[64];
    int tid = threadIdx.x;
    if (tid < 64) {
        float acc = b1[tid];
        for (int k = 0; k < 28; k++) acc += pf[k] * W1[k * 64 + tid];
        t1[tid] = fmaxf(acc, 0.f);
    }
    __syncthreads();
    if (tid < 64) {
        float acc = b2[tid];
        for (int jj = 0; jj < 64; jj++) acc += t1[jj] * W2[jj * 64 + tid];
        spk[tid] = acc;
    }
    __syncthreads();
    for (int idx = tid; idx < 64 * HH; idx += blockDim.x) {
        int o = idx / HH, i2 = idx % HH;
        const float4* wrow = (const float4*)(bilW + ((long long)o * HH + i2) * 64);
        float acc = 0.f;
        #pragma unroll
        for (int jj = 0; jj < 16; jj++) {
            float4 w = __ldg(&wrow[jj]);
            const float4 s = *(const float4*)&spk[jj * 4];
            acc += w.x * s.x + w.y * s.y + w.z * s.z + w.w * s.w;
        }
        g_Wp[o * HH + i2] = acc;
    }
}

// ---------------- pool (binary search) + bilinear + classifier ----------------
__global__ void k_pool_final(const void* __restrict__ batch,
                             const float* __restrict__ bil_b,
                             const float* __restrict__ cW1, const float* __restrict__ cb1,
                             const float* __restrict__ cW2, const float* __restrict__ cb2,
                             float* __restrict__ out) {
    __shared__ int   sLo, sHi;
    __shared__ float lig[HH];
    __shared__ float inter[64];
    __shared__ float c1[32];
    int g = blockIdx.x;
    int tid = threadIdx.x;
    int is64 = g_is64;
    if (tid < 2) {
        int key = g + tid;            // lower_bound(batch, key)
        int lo = 0, hi = NN;
        while (lo < hi) {
            int mid = (lo + hi) >> 1;
            if (load_idx(batch, mid, is64) < key) lo = mid + 1; else hi = mid;
        }
        if (tid == 0) sLo = lo; else sHi = lo;
    }
    __syncthreads();
    int lo = sLo, hi = sHi;
    float s0 = 0.f, s1 = 0.f;
    for (int r = lo; r < hi; r++) {
        s0 += g_h[(long long)r * HH + tid];
        s1 += g_h[(long long)r * HH + tid + 64];
    }
    float cnt = fmaxf((float)(hi - lo), 1.f);
    lig[tid]      = s0 / cnt;
    lig[tid + 64] = s1 / cnt;
    __syncthreads();
    {
        float acc = bil_b[tid];
        const float* wp = &g_Wp[tid * HH];
        #pragma unroll 8
        for (int i = 0; i < HH; i++) acc += lig[i] * wp[i];
        inter[tid] = acc;
    }
    __syncthreads();
    if (tid < 32) {
        float acc = cb1[tid];
        #pragma unroll 8
        for (int o = 0; o < 64; o++) acc += inter[o] * cW1[o * 32 + tid];
        c1[tid] = fmaxf(acc, 0.f);
    }
    __syncthreads();
    if (tid == 0) {
        float acc = cb2[0];
        #pragma unroll
        for (int t = 0; t < 32; t++) acc += c1[t] * cW2[t];
        out[g] = acc;
    }
}

// ---------------- launch --------------------------------------------------------
extern "C" void kernel_launch(void* const* d_in, const int* in_sizes, int n_in,
                              void* d_out, int out_size) {
    const float* x       = (const float*)d_in[0];
    const void*  ei      = d_in[1];
    const void*  batch   = d_in[2];
    const float* pocket  = (const float*)d_in[3];
    const float* conv0_W = (const float*)d_in[4];
    const float* conv0_b = (const float*)d_in[5];
    const float* convs_W = (const float*)d_in[6];
    const float* convs_b = (const float*)d_in[7];
    const float* bn_g    = (const float*)d_in[8];
    const float* bn_b    = (const float*)d_in[9];
    const float* bn_m    = (const float*)d_in[10];
    const float* bn_v    = (const float*)d_in[11];
    const float* pW1     = (const float*)d_in[12];
    const float* pb1     = (const float*)d_in[13];
    const float* pW2     = (const float*)d_in[14];
    const float* pb2     = (const float*)d_in[15];
    const float* bilW    = (const float*)d_in[16];
    const float* bilb    = (const float*)d_in[17];
    const float* cW1     = (const float*)d_in[18];
    const float* cb1     = (const float*)d_in[19];
    const float* cW2     = (const float*)d_in[20];
    const float* cb2     = (const float*)d_in[21];
    float* out = (float*)d_out;

    float* h = nullptr; __half* hw16 = nullptr; int* degp = nullptr;
    cudaGetSymbolAddress((void**)&h,    g_h);
    cudaGetSymbolAddress((void**)&hw16, g_hw16);
    cudaGetSymbolAddress((void**)&degp, g_deg);

    const int TB = 256;
    // CSR build
    k_detect<<<1, 32>>>(ei);
    k_small<<<1, 256>>>(pocket, pW1, pb1, pW2, pb2, bilW);   // independent, early
    cudaMemsetAsync(degp, 0, NN * sizeof(int));
    k_deg_count<<<(NE / 2 + TB - 1) / TB, TB>>>(ei);
    k_scanA<<<NB, 1024>>>();
    k_scanB<<<1, 32>>>();
    k_scanC<<<NB, 1024>>>();
    k_scatter<<<(NE / 2 + TB - 1) / TB, TB>>>(ei);

    int agg_blocks = (NN * 32 + TB - 1) / TB;

    // layer 0
    k_gemm0<<<(NN + 7) / 8, HH>>>(x, conv0_W);
    k_agg<<<agg_blocks, TB>>>(hw16, h, conv0_b,
                              bn_g + 0 * HH, bn_b + 0 * HH, bn_m + 0 * HH, bn_v + 0 * HH);
    // layers 1,2
    for (int l = 1; l <= 2; l++) {
        const float* W = convs_W + (long long)(l - 1) * HH * HH;
        const float* b = convs_b + (l - 1) * HH;
        k_gemm<<<(NN + 63) / 64, 128>>>(h, W, hw16);
        k_agg<<<agg_blocks, TB>>>(hw16, h, b,
                                  bn_g + l * HH, bn_b + l * HH, bn_m + l * HH, bn_v + l * HH);
    }

    // pool + bilinear + classifier (one block per graph, 64 threads)
    k_pool_final<<<GG, 64>>>(batch, bilb, cW1, cb1, cW2, cb2, out);
}

// round 6
// speedup vs baseline: 2.2801x; 1.0888x over previous
#include <cuda_runtime.h>
#include <cuda_fp16.h>

#define NN 50000
#define NE 1600000
#define HH 128
#define GG 256
#define BN_EPS 1e-5f
#define NB ((NN + 1023) / 1024)   // 49 scan blocks

// ---------------- scratch (static device memory) ----------------------------
__device__ int    g_is64;
__device__ int    g_deg[NN];
__device__ int    g_rowoff[NN + 1];
__device__ int    g_cursor[NN];
__device__ int2   g_edge[NE];          // {src, coef bits}
__device__ float  g_dinv[NN];
__device__ int    g_bsum[NB];
__device__ int    g_boff[NB];
__device__ __half g_x16[NN * 8];       // padded 7->8 fp16 input features
__device__ __half g_u016[NN * 8];      // aggregated layer-0 input
__device__ __half g_u16[NN * HH];      // agg output (128-dim)
__device__ __half g_h16[NN * HH];      // gemm output (post BN+ReLU)
__device__ float  g_Wp[64 * HH];

__device__ __forceinline__ int load_idx(const void* p, long long i, int is64) {
    if (is64) return (int)((const long long*)p)[i];
    return ((const int*)p)[i];
}
__device__ __forceinline__ int h2i(__half2 h) { return *reinterpret_cast<int*>(&h); }

// ---------------- dtype detection -------------------------------------------
__global__ void k_detect(const void* ei) {
    const int* p = (const int*)ei;
    int lane = threadIdx.x;
    int nz = 0;
    #pragma unroll
    for (int r = 0; r < 4; r++) if (p[(lane + r * 32) * 2 + 1] != 0) nz = 1;
    unsigned m = __ballot_sync(0xFFFFFFFFu, nz);
    if (lane == 0) g_is64 = (m == 0u) ? 1 : 0;
}

// ---------------- CSR build ---------------------------------------------------
__global__ void k_deg_count(const void* ei) {
    int t = blockIdx.x * blockDim.x + threadIdx.x;
    if (t >= NE / 2) return;
    int d0, d1;
    if (g_is64) {
        int4 v = __ldg((const int4*)((const long long*)ei + NE) + t);
        d0 = v.x; d1 = v.z;
    } else {
        int2 v = __ldg((const int2*)((const int*)ei + NE) + t);
        d0 = v.x; d1 = v.y;
    }
    atomicAdd(&g_deg[d0], 1);
    atomicAdd(&g_deg[d1], 1);
}

__global__ void k_scanA() {
    int i = blockIdx.x * 1024 + threadIdx.x;
    int v = (i < NN) ? g_deg[i] : 0;
    int lane = threadIdx.x & 31, wid = threadIdx.x >> 5;
    int s = v;
    #pragma unroll
    for (int o = 1; o < 32; o <<= 1) {
        int t = __shfl_up_sync(0xFFFFFFFFu, s, o);
        if (lane >= o) s += t;
    }
    __shared__ int wsum[32];
    if (lane == 31) wsum[wid] = s;
    __syncthreads();
    if (wid == 0) {
        int t = wsum[lane];
        #pragma unroll
        for (int o = 1; o < 32; o <<= 1) {
            int u = __shfl_up_sync(0xFFFFFFFFu, t, o);
            if (lane >= o) t += u;
        }
        wsum[lane] = t;
    }
    __syncthreads();
    int incl = s + (wid > 0 ? wsum[wid - 1] : 0);
    if (i < NN) {
        g_rowoff[i] = incl - v;
        g_dinv[i]   = rsqrtf((float)v + 1.0f);
    }
    if (threadIdx.x == 1023) g_bsum[blockIdx.x] = incl;
}

__global__ void k_scanB() {
    int lane = threadIdx.x;
    int carry = 0;
    for (int base = 0; base < NB; base += 32) {
        int idx = base + lane;
        int v = (idx < NB) ? g_bsum[idx] : 0;
        int s = v;
        #pragma unroll
        for (int o = 1; o < 32; o <<= 1) {
            int t = __shfl_up_sync(0xFFFFFFFFu, s, o);
            if (lane >= o) s += t;
        }
        if (idx < NB) g_boff[idx] = carry + s - v;
        carry += __shfl_sync(0xFFFFFFFFu, s, 31);
    }
    if (lane == 0) g_rowoff[NN] = carry;
}

__global__ void k_scanC() {
    int i = blockIdx.x * 1024 + threadIdx.x;
    if (i < NN) {
        int v = g_rowoff[i] + g_boff[blockIdx.x];
        g_rowoff[i] = v;
        g_cursor[i] = v;
    }
}

__global__ void k_scatter(const void* ei) {
    int t = blockIdx.x * blockDim.x + threadIdx.x;
    if (t >= NE / 2) return;
    int s0, s1, d0, d1;
    if (g_is64) {
        int4 sv = __ldg((const int4*)((const long long*)ei) + t);
        int4 dv = __ldg((const int4*)((const long long*)ei + NE) + t);
        s0 = sv.x; s1 = sv.z; d0 = dv.x; d1 = dv.z;
    } else {
        int2 sv = __ldg((const int2*)((const int*)ei) + t);
        int2 dv = __ldg((const int2*)((const int*)ei + NE) + t);
        s0 = sv.x; s1 = sv.y; d0 = dv.x; d1 = dv.y;
    }
    float c0 = g_dinv[s0] * g_dinv[d0];
    float c1 = g_dinv[s1] * g_dinv[d1];
    int p0 = atomicAdd(&g_cursor[d0], 1);
    g_edge[p0] = make_int2(s0, __float_as_int(c0));
    int p1 = atomicAdd(&g_cursor[d1], 1);
    g_edge[p1] = make_int2(s1, __float_as_int(c1));
}

// ---------------- x -> fp16 padded [N,8] --------------------------------------
__global__ void k_prep_x(const float* __restrict__ x) {
    int v = blockIdx.x * blockDim.x + threadIdx.x;
    if (v >= NN) return;
    __half h[8];
    #pragma unroll
    for (int k = 0; k < 7; k++) h[k] = __float2half_rn(x[v * 7 + k]);
    h[7] = __float2half_rn(0.f);
    *(uint4*)&g_x16[v * 8] = *(uint4*)h;
}

// ---------------- layer-0 aggregation in 7-dim space (thread per node) --------
__global__ void k_aggx() {
    int v = blockIdx.x * blockDim.x + threadIdx.x;
    if (v >= NN) return;
    float di = g_dinv[v];
    float c0 = di * di;
    float acc[8];
    {
        uint4 u = *(const uint4*)&g_x16[v * 8];
        const __half2* hp = (const __half2*)&u;
        #pragma unroll
        for (int q = 0; q < 4; q++) {
            float2 f = __half22float2(hp[q]);
            acc[q * 2] = c0 * f.x; acc[q * 2 + 1] = c0 * f.y;
        }
    }
    int e0 = g_rowoff[v], e1 = g_rowoff[v + 1];
    int e = e0;
    for (; e + 1 < e1; e += 2) {
        int2 eA = __ldg(&g_edge[e]);
        int2 eB = __ldg(&g_edge[e + 1]);
        uint4 uA = __ldg((const uint4*)&g_x16[(long long)eA.x * 8]);
        uint4 uB = __ldg((const uint4*)&g_x16[(long long)eB.x * 8]);
        float cA = __int_as_float(eA.y), cB = __int_as_float(eB.y);
        const __half2* ha = (const __half2*)&uA;
        const __half2* hb = (const __half2*)&uB;
        #pragma unroll
        for (int q = 0; q < 4; q++) {
            float2 fa = __half22float2(ha[q]);
            float2 fb = __half22float2(hb[q]);
            acc[q * 2]     += cA * fa.x + cB * fb.x;
            acc[q * 2 + 1] += cA * fa.y + cB * fb.y;
        }
    }
    for (; e < e1; e++) {
        int2 ed = __ldg(&g_edge[e]);
        uint4 u = __ldg((const uint4*)&g_x16[(long long)ed.x * 8]);
        float c = __int_as_float(ed.y);
        const __half2* hp = (const __half2*)&u;
        #pragma unroll
        for (int q = 0; q < 4; q++) {
            float2 f = __half22float2(hp[q]);
            acc[q * 2] += c * f.x; acc[q * 2 + 1] += c * f.y;
        }
    }
    __half2 o[4];
    #pragma unroll
    for (int q = 0; q < 4; q++) o[q] = __floats2half2_rn(acc[q * 2], acc[q * 2 + 1]);
    *(uint4*)&g_u016[v * 8] = *(uint4*)o;
}

// ---------------- layer-0 GEMM: h1 = ReLU(BN0(u0 @ W0 + b0)) -------------------
__global__ void k_gemm0(const float* __restrict__ W, const float* __restrict__ bias,
                        const float* __restrict__ gamma, const float* __restrict__ beta,
                        const float* __restrict__ mean,  const float* __restrict__ var) {
    __shared__ float su[32][8];
    int row0 = blockIdx.x * 32;
    int tid = threadIdx.x;     // 128 threads = one col each
    if (tid < 32) {
        int gr = row0 + tid;
        uint4 u = (gr < NN) ? *(const uint4*)&g_u016[gr * 8]
                            : make_uint4(0, 0, 0, 0);
        const __half2* hp = (const __half2*)&u;
        #pragma unroll
        for (int q = 0; q < 4; q++) {
            float2 f = __half22float2(hp[q]);
            su[tid][q * 2] = f.x; su[tid][q * 2 + 1] = f.y;
        }
    }
    __syncthreads();
    float w[7];
    #pragma unroll
    for (int k = 0; k < 7; k++) w[k] = W[k * HH + tid];
    float rs = rsqrtf(var[tid] + BN_EPS);
    float scale = gamma[tid] * rs;
    float shift = (bias[tid] - mean[tid]) * scale + beta[tid];
    #pragma unroll 4
    for (int r = 0; r < 32; r++) {
        int gr = row0 + r;
        if (gr < NN) {
            float acc = 0.f;
            #pragma unroll
            for (int k = 0; k < 7; k++) acc += su[r][k] * w[k];
            g_h16[(long long)gr * HH + tid] = __float2half_rn(fmaxf(acc * scale + shift, 0.f));
        }
    }
}

// ---------------- 128-dim aggregation: u = Â h  (fp16 in/out) ------------------
__global__ void k_agg(const __half* __restrict__ in16, __half* __restrict__ out16) {
    int v = (blockIdx.x * blockDim.x + threadIdx.x) >> 5;
    int lane = threadIdx.x & 31;
    if (v >= NN) return;
    float di = g_dinv[v];
    float c0 = di * di;
    int j = lane * 4;
    uint2 us = __ldg((const uint2*)(in16 + (long long)v * HH + j));
    float2 s0 = __half22float2(*(const __half2*)&us.x);
    float2 s1 = __half22float2(*(const __half2*)&us.y);
    float ax = c0 * s0.x, ay = c0 * s0.y, az = c0 * s1.x, aw = c0 * s1.y;
    int e0 = g_rowoff[v], e1 = g_rowoff[v + 1];
    int e = e0;
    for (; e + 7 < e1; e += 8) {
        int2 ed[8];
        uint2 u[8];
        #pragma unroll
        for (int q = 0; q < 8; q++) ed[q] = __ldg(&g_edge[e + q]);
        #pragma unroll
        for (int q = 0; q < 8; q++)
            u[q] = __ldg((const uint2*)(in16 + (long long)ed[q].x * HH + j));
        #pragma unroll
        for (int q = 0; q < 8; q++) {
            float c = __int_as_float(ed[q].y);
            float2 f0 = __half22float2(*(const __half2*)&u[q].x);
            float2 f1 = __half22float2(*(const __half2*)&u[q].y);
            ax += c * f0.x; ay += c * f0.y; az += c * f1.x; aw += c * f1.y;
        }
    }
    for (; e < e1; e++) {
        int2 ed = __ldg(&g_edge[e]);
        float c = __int_as_float(ed.y);
        uint2 u = __ldg((const uint2*)(in16 + (long long)ed.x * HH + j));
        float2 f0 = __half22float2(*(const __half2*)&u.x);
        float2 f1 = __half22float2(*(const __half2*)&u.y);
        ax += c * f0.x; ay += c * f0.y; az += c * f1.x; aw += c * f1.y;
    }
    uint2 o;
    *(__half2*)&o.x = __floats2half2_rn(ax, ay);
    *(__half2*)&o.y = __floats2half2_rn(az, aw);
    *(uint2*)(out16 + (long long)v * HH + j) = o;
}

// ---------------- GEMM + fused bias/BN/ReLU: h = act(u @ W) --------------------
// 64 rows/block, 128 threads, 8x8 register tile, fp16 in/out
__global__ void __launch_bounds__(128) k_gemm(const __half* __restrict__ A16,
                                              const float* __restrict__ W,
                                              __half* __restrict__ C16,
                                              const float* __restrict__ bias,
                                              const float* __restrict__ gamma,
                                              const float* __restrict__ beta,
                                              const float* __restrict__ mean,
                                              const float* __restrict__ var) {
    __shared__ float sA[64][HH];
    int row0 = blockIdx.x * 64;
    int tid = threadIdx.x;
    // stage A: 64 rows x 128 halfs = 1024 uint4, 8 per thread
    for (int i = tid; i < 64 * 16; i += 128) {
        int r = i >> 4, c8 = i & 15;
        int gr = row0 + r;
        uint4 u = (gr < NN) ? *(const uint4*)&A16[(long long)gr * HH + c8 * 8]
                            : make_uint4(0, 0, 0, 0);
        const __half2* hp = (const __half2*)&u;
        float out[8];
        #pragma unroll
        for (int q = 0; q < 4; q++) {
            float2 f = __half22float2(hp[q]);
            out[q * 2] = f.x; out[q * 2 + 1] = f.y;
        }
        *(float4*)&sA[r][c8 * 8]     = *(float4*)&out[0];
        *(float4*)&sA[r][c8 * 8 + 4] = *(float4*)&out[4];
    }
    __syncthreads();
    int cg = tid & 15;
    int rg = tid >> 4;
    float acc[8][8] = {};
    for (int k0 = 0; k0 < HH; k0 += 4) {
        float4 wv[4][2];
        #pragma unroll
        for (int kk = 0; kk < 4; kk++) {
            wv[kk][0] = __ldg((const float4*)&W[(k0 + kk) * HH + cg * 8]);
            wv[kk][1] = __ldg((const float4*)&W[(k0 + kk) * HH + cg * 8 + 4]);
        }
        #pragma unroll
        for (int r = 0; r < 8; r++) {
            float4 a = *(const float4*)&sA[rg * 8 + r][k0];
            #pragma unroll
            for (int kk = 0; kk < 4; kk++) {
                float av = (kk == 0) ? a.x : (kk == 1) ? a.y : (kk == 2) ? a.z : a.w;
                acc[r][0] += av * wv[kk][0].x; acc[r][1] += av * wv[kk][0].y;
                acc[r][2] += av * wv[kk][0].z; acc[r][3] += av * wv[kk][0].w;
                acc[r][4] += av * wv[kk][1].x; acc[r][5] += av * wv[kk][1].y;
                acc[r][6] += av * wv[kk][1].z; acc[r][7] += av * wv[kk][1].w;
            }
        }
    }
    // fused epilogue: scale/shift per column
    float sc[8], sh[8];
    {
        float4 g0 = *(const float4*)&gamma[cg * 8], g1 = *(const float4*)&gamma[cg * 8 + 4];
        float4 v0 = *(const float4*)&var[cg * 8],   v1 = *(const float4*)&var[cg * 8 + 4];
        float4 m0 = *(const float4*)&mean[cg * 8],  m1 = *(const float4*)&mean[cg * 8 + 4];
        float4 b0 = *(const float4*)&bias[cg * 8],  b1 = *(const float4*)&bias[cg * 8 + 4];
        float4 t0 = *(const float4*)&beta[cg * 8],  t1 = *(const float4*)&beta[cg * 8 + 4];
        const float* gp = (const float*)&g0; const float* g2 = (const float*)&g1;
        const float* vp = (const float*)&v0; const float* v2 = (const float*)&v1;
        const float* mp = (const float*)&m0; const float* m2 = (const float*)&m1;
        const float* bp = (const float*)&b0; const float* b2 = (const float*)&b1;
        const float* tp = (const float*)&t0; const float* t2 = (const float*)&t1;
        #pragma unroll
        for (int q = 0; q < 4; q++) {
            sc[q] = gp[q] * rsqrtf(vp[q] + BN_EPS);
            sh[q] = (bp[q] - mp[q]) * sc[q] + tp[q];
            sc[q + 4] = g2[q] * rsqrtf(v2[q] + BN_EPS);
            sh[q + 4] = (b2[q] - m2[q]) * sc[q + 4] + t2[q];
        }
    }
    #pragma unroll
    for (int r = 0; r < 8; r++) {
        int gr = row0 + rg * 8 + r;
        if (gr < NN) {
            float o[8];
            #pragma unroll
            for (int q = 0; q < 8; q++) o[q] = fmaxf(acc[r][q] * sc[q] + sh[q], 0.f);
            __half2 h0 = __floats2half2_rn(o[0], o[1]);
            __half2 h1 = __floats2half2_rn(o[2], o[3]);
            __half2 h2 = __floats2half2_rn(o[4], o[5]);
            __half2 h3 = __floats2half2_rn(o[6], o[7]);
            int4 pk = make_int4(h2i(h0), h2i(h1), h2i(h2), h2i(h3));
            *(int4*)&C16[(long long)gr * HH + cg * 8] = pk;
        }
    }
}

// ---------------- pocket MLP + bilinear weight contraction --------------------
__global__ void k_small(const float* __restrict__ pf,
                        const float* __restrict__ W1, const float* __restrict__ b1,
                        const float* __restrict__ W2, const float* __restrict__ b2,
                        const float* __restrict__ bilW) {
    __shared__ float t1[64];
    __shared__ float spk[64];
    int tid = threadIdx.x;
    if (tid < 64) {
        float acc = b1[tid];
        for (int k = 0; k < 28; k++) acc += pf[k] * W1[k * 64 + tid];
        t1[tid] = fmaxf(acc, 0.f);
    }
    __syncthreads();
    if (tid < 64) {
        float acc = b2[tid];
        for (int jj = 0; jj < 64; jj++) acc += t1[jj] * W2[jj * 64 + tid];
        spk[tid] = acc;
    }
    __syncthreads();
    for (int idx = tid; idx < 64 * HH; idx += blockDim.x) {
        int o = idx / HH, i2 = idx % HH;
        const float4* wrow = (const float4*)(bilW + ((long long)o * HH + i2) * 64);
        float acc = 0.f;
        #pragma unroll
        for (int jj = 0; jj < 16; jj++) {
            float4 w = __ldg(&wrow[jj]);
            const float4 s = *(const float4*)&spk[jj * 4];
            acc += w.x * s.x + w.y * s.y + w.z * s.z + w.w * s.w;
        }
        g_Wp[o * HH + i2] = acc;
    }
}

// ---------------- pool + bilinear + classifier --------------------------------
__global__ void k_pool_final(const void* __restrict__ batch,
                             const float* __restrict__ bil_b,
                             const float* __restrict__ cW1, const float* __restrict__ cb1,
                             const float* __restrict__ cW2, const float* __restrict__ cb2,
                             float* __restrict__ out) {
    __shared__ int   sLo, sHi;
    __shared__ float lig[HH];
    __shared__ float inter[64];
    __shared__ float c1[32];
    int g = blockIdx.x;
    int tid = threadIdx.x;   // 64 threads
    int is64 = g_is64;
    if (tid < 2) {
        int key = g + tid;
        int lo = 0, hi = NN;
        while (lo < hi) {
            int mid = (lo + hi) >> 1;
            if (load_idx(batch, mid, is64) < key) lo = mid + 1; else hi = mid;
        }
        if (tid == 0) sLo = lo; else sHi = lo;
    }
    __syncthreads();
    int lo = sLo, hi = sHi;
    float s0 = 0.f, s1 = 0.f;
    for (int r = lo; r < hi; r++) {
        uint u0 = __ldg((const uint*)(g_h16 + (long long)r * HH + tid * 2));
        // thread covers features 2*tid, 2*tid+1 (first half) and +64 pair
        float2 f0 = __half22float2(*(const __half2*)&u0);
        s0 += f0.x; s1 += f0.y;
    }
    float cnt = fmaxf((float)(hi - lo), 1.f);
    lig[tid * 2]     = s0 / cnt;
    lig[tid * 2 + 1] = s1 / cnt;
    __syncthreads();
    {
        float acc = bil_b[tid];
        const float* wp = &g_Wp[tid * HH];
        #pragma unroll 8
        for (int i = 0; i < HH; i++) acc += lig[i] * wp[i];
        inter[tid] = acc;
    }
    __syncthreads();
    if (tid < 32) {
        float acc = cb1[tid];
        #pragma unroll 8
        for (int o = 0; o < 64; o++) acc += inter[o] * cW1[o * 32 + tid];
        c1[tid] = fmaxf(acc, 0.f);
    }
    __syncthreads();
    if (tid == 0) {
        float acc = cb2[0];
        #pragma unroll
        for (int t = 0; t < 32; t++) acc += c1[t] * cW2[t];
        out[g] = acc;
    }
}

// ---------------- launch --------------------------------------------------------
extern "C" void kernel_launch(void* const* d_in, const int* in_sizes, int n_in,
                              void* d_out, int out_size) {
    const float* x       = (const float*)d_in[0];
    const void*  ei      = d_in[1];
    const void*  batch   = d_in[2];
    const float* pocket  = (const float*)d_in[3];
    const float* conv0_W = (const float*)d_in[4];
    const float* conv0_b = (const float*)d_in[5];
    const float* convs_W = (const float*)d_in[6];
    const float* convs_b = (const float*)d_in[7];
    const float* bn_g    = (const float*)d_in[8];
    const float* bn_b    = (const float*)d_in[9];
    const float* bn_m    = (const float*)d_in[10];
    const float* bn_v    = (const float*)d_in[11];
    const float* pW1     = (const float*)d_in[12];
    const float* pb1     = (const float*)d_in[13];
    const float* pW2     = (const float*)d_in[14];
    const float* pb2     = (const float*)d_in[15];
    const float* bilW    = (const float*)d_in[16];
    const float* bilb    = (const float*)d_in[17];
    const float* cW1     = (const float*)d_in[18];
    const float* cb1     = (const float*)d_in[19];
    const float* cW2     = (const float*)d_in[20];
    const float* cb2     = (const float*)d_in[21];
    float* out = (float*)d_out;

    __half* h16 = nullptr; __half* u16 = nullptr; int* degp = nullptr;
    cudaGetSymbolAddress((void**)&h16, g_h16);
    cudaGetSymbolAddress((void**)&u16, g_u16);
    cudaGetSymbolAddress((void**)&degp, g_deg);

    const int TB = 256;
    // CSR build + input prep
    k_detect<<<1, 32>>>(ei);
    k_small<<<1, 256>>>(pocket, pW1, pb1, pW2, pb2, bilW);
    k_prep_x<<<(NN + TB - 1) / TB, TB>>>(x);
    cudaMemsetAsync(degp, 0, NN * sizeof(int));
    k_deg_count<<<(NE / 2 + TB - 1) / TB, TB>>>(ei);
    k_scanA<<<NB, 1024>>>();
    k_scanB<<<1, 32>>>();
    k_scanC<<<NB, 1024>>>();
    k_scatter<<<(NE / 2 + TB - 1) / TB, TB>>>(ei);

    int agg_blocks = (NN * 32 + TB - 1) / TB;

    // layer 0: aggregate x (7-dim) then GEMM+BN+ReLU
    k_aggx<<<(NN + TB - 1) / TB, TB>>>();
    k_gemm0<<<(NN + 31) / 32, HH>>>(conv0_W, conv0_b,
                                    bn_g, bn_b, bn_m, bn_v);
    // layers 1,2: aggregate h (128-dim) then GEMM+BN+ReLU
    for (int l = 1; l <= 2; l++) {
        const float* W = convs_W + (long long)(l - 1) * HH * HH;
        const float* b = convs_b + (l - 1) * HH;
        k_agg<<<agg_blocks, TB>>>(h16, u16);
        k_gemm<<<(NN + 63) / 64, 128>>>(u16, W, h16, b,
                                        bn_g + l * HH, bn_b + l * HH,
                                        bn_m + l * HH, bn_v + l * HH);
    }

    // pool + bilinear + classifier
    k_pool_final<<<GG, 64>>>(batch, bilb, cW1, cb1, cW2, cb2, out);
}

// round 7
// speedup vs baseline: 2.4718x; 1.0841x over previous
#include <cuda_runtime.h>
#include <cuda_fp16.h>
#include <mma.h>
using namespace nvcuda;

#define NN 50000
#define NP 50048                 // padded to 64-row multiple
#define NE 1600000
#define HH 128
#define GG 256
#define BN_EPS 1e-5f
#define NB ((NN + 1023) / 1024)

// ---------------- scratch (static device memory) ----------------------------
__device__ int    g_is64;
__device__ int    g_deg[NN];
__device__ int    g_rowoff[NN + 1];
__device__ int    g_cursor[NN];
__device__ int2   g_edge[NE];
__device__ float  g_dinv[NN];
__device__ int    g_bsum[NB];
__device__ int    g_boff[NB];
__device__ __half g_x16[NN * 8];
__device__ __half g_u016[NN * 8];
__device__ __half g_u16[NP * HH];
__device__ __half g_h16[NP * HH];
__device__ __half g_W16[2 * HH * HH];
__device__ float  g_Wp[64 * HH];

__device__ __forceinline__ int load_idx(const void* p, long long i, int is64) {
    if (is64) return (int)((const long long*)p)[i];
    return ((const int*)p)[i];
}
__device__ __forceinline__ int h2i(__half2 h) { return *reinterpret_cast<int*>(&h); }

// ---------------- dtype detection -------------------------------------------
__global__ void k_detect(const void* ei) {
    const int* p = (const int*)ei;
    int lane = threadIdx.x;
    int nz = 0;
    #pragma unroll
    for (int r = 0; r < 4; r++) if (p[(lane + r * 32) * 2 + 1] != 0) nz = 1;
    unsigned m = __ballot_sync(0xFFFFFFFFu, nz);
    if (lane == 0) g_is64 = (m == 0u) ? 1 : 0;
}

// ---------------- CSR build: 4 edges per thread --------------------------------
__global__ void k_deg_count(const void* ei) {
    int t = blockIdx.x * blockDim.x + threadIdx.x;
    if (t >= NE / 4) return;
    int d[4];
    if (g_is64) {
        int4 v0 = __ldg((const int4*)((const long long*)ei + NE) + t * 2);
        int4 v1 = __ldg((const int4*)((const long long*)ei + NE) + t * 2 + 1);
        d[0] = v0.x; d[1] = v0.z; d[2] = v1.x; d[3] = v1.z;
    } else {
        int4 v = __ldg((const int4*)((const int*)ei + NE) + t);
        d[0] = v.x; d[1] = v.y; d[2] = v.z; d[3] = v.w;
    }
    #pragma unroll
    for (int q = 0; q < 4; q++) atomicAdd(&g_deg[d[q]], 1);
}

__global__ void k_scanA() {
    int i = blockIdx.x * 1024 + threadIdx.x;
    int v = (i < NN) ? g_deg[i] : 0;
    int lane = threadIdx.x & 31, wid = threadIdx.x >> 5;
    int s = v;
    #pragma unroll
    for (int o = 1; o < 32; o <<= 1) {
        int t = __shfl_up_sync(0xFFFFFFFFu, s, o);
        if (lane >= o) s += t;
    }
    __shared__ int wsum[32];
    if (lane == 31) wsum[wid] = s;
    __syncthreads();
    if (wid == 0) {
        int t = wsum[lane];
        #pragma unroll
        for (int o = 1; o < 32; o <<= 1) {
            int u = __shfl_up_sync(0xFFFFFFFFu, t, o);
            if (lane >= o) t += u;
        }
        wsum[lane] = t;
    }
    __syncthreads();
    int incl = s + (wid > 0 ? wsum[wid - 1] : 0);
    if (i < NN) {
        g_rowoff[i] = incl - v;
        g_dinv[i]   = rsqrtf((float)v + 1.0f);
    }
    if (threadIdx.x == 1023) g_bsum[blockIdx.x] = incl;
}

__global__ void k_scanB() {
    int lane = threadIdx.x;
    int carry = 0;
    for (int base = 0; base < NB; base += 32) {
        int idx = base + lane;
        int v = (idx < NB) ? g_bsum[idx] : 0;
        int s = v;
        #pragma unroll
        for (int o = 1; o < 32; o <<= 1) {
            int t = __shfl_up_sync(0xFFFFFFFFu, s, o);
            if (lane >= o) s += t;
        }
        if (idx < NB) g_boff[idx] = carry + s - v;
        carry += __shfl_sync(0xFFFFFFFFu, s, 31);
    }
    if (lane == 0) g_rowoff[NN] = carry;
}

__global__ void k_scanC() {
    int i = blockIdx.x * 1024 + threadIdx.x;
    if (i < NN) {
        int v = g_rowoff[i] + g_boff[blockIdx.x];
        g_rowoff[i] = v;
        g_cursor[i] = v;
    }
}

__global__ void k_scatter(const void* ei) {
    int t = blockIdx.x * blockDim.x + threadIdx.x;
    if (t >= NE / 4) return;
    int s[4], d[4];
    if (g_is64) {
        int4 s0 = __ldg((const int4*)((const long long*)ei) + t * 2);
        int4 s1 = __ldg((const int4*)((const long long*)ei) + t * 2 + 1);
        int4 d0 = __ldg((const int4*)((const long long*)ei + NE) + t * 2);
        int4 d1 = __ldg((const int4*)((const long long*)ei + NE) + t * 2 + 1);
        s[0] = s0.x; s[1] = s0.z; s[2] = s1.x; s[3] = s1.z;
        d[0] = d0.x; d[1] = d0.z; d[2] = d1.x; d[3] = d1.z;
    } else {
        int4 sv = __ldg((const int4*)((const int*)ei) + t);
        int4 dv = __ldg((const int4*)((const int*)ei + NE) + t);
        s[0] = sv.x; s[1] = sv.y; s[2] = sv.z; s[3] = sv.w;
        d[0] = dv.x; d[1] = dv.y; d[2] = dv.z; d[3] = dv.w;
    }
    #pragma unroll
    for (int q = 0; q < 4; q++) {
        float c = g_dinv[s[q]] * g_dinv[d[q]];
        int pos = atomicAdd(&g_cursor[d[q]], 1);
        g_edge[pos] = make_int2(s[q], __float_as_int(c));
    }
}

// ---------------- x -> fp16 padded [N,8]; W -> fp16 ---------------------------
__global__ void k_prep_x(const float* __restrict__ x) {
    int v = blockIdx.x * blockDim.x + threadIdx.x;
    if (v >= NN) return;
    __half h[8];
    #pragma unroll
    for (int k = 0; k < 7; k++) h[k] = __float2half_rn(x[v * 7 + k]);
    h[7] = __float2half_rn(0.f);
    *(uint4*)&g_x16[v * 8] = *(uint4*)h;
}

__global__ void k_w16(const float* __restrict__ W) {
    int i = blockIdx.x * blockDim.x + threadIdx.x;
    if (i < 2 * HH * HH) g_W16[i] = __float2half_rn(W[i]);
}

// ---------------- layer-0 aggregation in 7-dim space ---------------------------
__global__ void k_aggx() {
    int v = blockIdx.x * blockDim.x + threadIdx.x;
    if (v >= NN) return;
    float di = g_dinv[v];
    float c0 = di * di;
    float acc[8];
    {
        uint4 u = *(const uint4*)&g_x16[v * 8];
        const __half2* hp = (const __half2*)&u;
        #pragma unroll
        for (int q = 0; q < 4; q++) {
            float2 f = __half22float2(hp[q]);
            acc[q * 2] = c0 * f.x; acc[q * 2 + 1] = c0 * f.y;
        }
    }
    int e0 = g_rowoff[v], e1 = g_rowoff[v + 1];
    int e = e0;
    for (; e + 1 < e1; e += 2) {
        int2 eA = __ldg(&g_edge[e]);
        int2 eB = __ldg(&g_edge[e + 1]);
        uint4 uA = __ldg((const uint4*)&g_x16[(long long)eA.x * 8]);
        uint4 uB = __ldg((const uint4*)&g_x16[(long long)eB.x * 8]);
        float cA = __int_as_float(eA.y), cB = __int_as_float(eB.y);
        const __half2* ha = (const __half2*)&uA;
        const __half2* hb = (const __half2*)&uB;
        #pragma unroll
        for (int q = 0; q < 4; q++) {
            float2 fa = __half22float2(ha[q]);
            float2 fb = __half22float2(hb[q]);
            acc[q * 2]     += cA * fa.x + cB * fb.x;
            acc[q * 2 + 1] += cA * fa.y + cB * fb.y;
        }
    }
    for (; e < e1; e++) {
        int2 ed = __ldg(&g_edge[e]);
        uint4 u = __ldg((const uint4*)&g_x16[(long long)ed.x * 8]);
        float c = __int_as_float(ed.y);
        const __half2* hp = (const __half2*)&u;
        #pragma unroll
        for (int q = 0; q < 4; q++) {
            float2 f = __half22float2(hp[q]);
            acc[q * 2] += c * f.x; acc[q * 2 + 1] += c * f.y;
        }
    }
    __half2 o[4];
    #pragma unroll
    for (int q = 0; q < 4; q++) o[q] = __floats2half2_rn(acc[q * 2], acc[q * 2 + 1]);
    *(uint4*)&g_u016[v * 8] = *(uint4*)o;
}

// ---------------- layer-0 GEMM + BN + ReLU -------------------------------------
__global__ void k_gemm0(const float* __restrict__ W, const float* __restrict__ bias,
                        const float* __restrict__ gamma, const float* __restrict__ beta,
                        const float* __restrict__ mean,  const float* __restrict__ var) {
    __shared__ float su[32][8];
    int row0 = blockIdx.x * 32;
    int tid = threadIdx.x;
    if (tid < 32) {
        int gr = row0 + tid;
        uint4 u = (gr < NN) ? *(const uint4*)&g_u016[gr * 8]
                            : make_uint4(0, 0, 0, 0);
        const __half2* hp = (const __half2*)&u;
        #pragma unroll
        for (int q = 0; q < 4; q++) {
            float2 f = __half22float2(hp[q]);
            su[tid][q * 2] = f.x; su[tid][q * 2 + 1] = f.y;
        }
    }
    __syncthreads();
    float w[7];
    #pragma unroll
    for (int k = 0; k < 7; k++) w[k] = W[k * HH + tid];
    float rs = rsqrtf(var[tid] + BN_EPS);
    float scale = gamma[tid] * rs;
    float shift = (bias[tid] - mean[tid]) * scale + beta[tid];
    #pragma unroll 4
    for (int r = 0; r < 32; r++) {
        int gr = row0 + r;
        if (gr < NN) {
            float acc = 0.f;
            #pragma unroll
            for (int k = 0; k < 7; k++) acc += su[r][k] * w[k];
            g_h16[(long long)gr * HH + tid] = __float2half_rn(fmaxf(acc * scale + shift, 0.f));
        }
    }
}

// ---------------- 128-dim aggregation ------------------------------------------
__global__ void k_agg(const __half* __restrict__ in16, __half* __restrict__ out16) {
    int v = (blockIdx.x * blockDim.x + threadIdx.x) >> 5;
    int lane = threadIdx.x & 31;
    if (v >= NN) return;
    float di = g_dinv[v];
    float c0 = di * di;
    int j = lane * 4;
    uint2 us = __ldg((const uint2*)(in16 + (long long)v * HH + j));
    float2 s0 = __half22float2(*(const __half2*)&us.x);
    float2 s1 = __half22float2(*(const __half2*)&us.y);
    float ax = c0 * s0.x, ay = c0 * s0.y, az = c0 * s1.x, aw = c0 * s1.y;
    int e0 = g_rowoff[v], e1 = g_rowoff[v + 1];
    int e = e0;
    for (; e + 7 < e1; e += 8) {
        int2 ed[8];
        uint2 u[8];
        #pragma unroll
        for (int q = 0; q < 8; q++) ed[q] = __ldg(&g_edge[e + q]);
        #pragma unroll
        for (int q = 0; q < 8; q++)
            u[q] = __ldg((const uint2*)(in16 + (long long)ed[q].x * HH + j));
        #pragma unroll
        for (int q = 0; q < 8; q++) {
            float c = __int_as_float(ed[q].y);
            float2 f0 = __half22float2(*(const __half2*)&u[q].x);
            float2 f1 = __half22float2(*(const __half2*)&u[q].y);
            ax += c * f0.x; ay += c * f0.y; az += c * f1.x; aw += c * f1.y;
        }
    }
    for (; e < e1; e++) {
        int2 ed = __ldg(&g_edge[e]);
        float c = __int_as_float(ed.y);
        uint2 u = __ldg((const uint2*)(in16 + (long long)ed.x * HH + j));
        float2 f0 = __half22float2(*(const __half2*)&u.x);
        float2 f1 = __half22float2(*(const __half2*)&u.y);
        ax += c * f0.x; ay += c * f0.y; az += c * f1.x; aw += c * f1.y;
    }
    uint2 o;
    *(__half2*)&o.x = __floats2half2_rn(ax, ay);
    *(__half2*)&o.y = __floats2half2_rn(az, aw);
    *(uint2*)(out16 + (long long)v * HH + j) = o;
}

// ---------------- tensor-core GEMM + fused BN/ReLU -----------------------------
// 64 rows/block, 4 warps; warp = 16-row strip x 128 cols; fragments from gmem
__global__ void __launch_bounds__(128) k_gemm_tc(const __half* __restrict__ A16,
                                                 const __half* __restrict__ W16,
                                                 __half* __restrict__ C16,
                                                 const float* __restrict__ bias,
                                                 const float* __restrict__ gamma,
                                                 const float* __restrict__ beta,
                                                 const float* __restrict__ mean,
                                                 const float* __restrict__ var) {
    __shared__ float sC[4][16 * HH];     // 32 KB
    __shared__ float s_sc[HH], s_sh[HH];
    int tid = threadIdx.x;
    int warp = tid >> 5, lane = tid & 31;
    {
        float rs = rsqrtf(var[tid] + BN_EPS);
        float sc = gamma[tid] * rs;
        s_sc[tid] = sc;
        s_sh[tid] = (bias[tid] - mean[tid]) * sc + beta[tid];
    }
    __syncthreads();

    int row0 = blockIdx.x * 64 + warp * 16;   // always < NP (padded)
    wmma::fragment<wmma::accumulator, 16, 16, 16, float> c_frag[8];
    #pragma unroll
    for (int n = 0; n < 8; n++) wmma::fill_fragment(c_frag[n], 0.0f);

    for (int k = 0; k < HH; k += 16) {
        wmma::fragment<wmma::matrix_a, 16, 16, 16, __half, wmma::row_major> a_frag;
        wmma::load_matrix_sync(a_frag, A16 + (long long)row0 * HH + k, HH);
        #pragma unroll
        for (int n = 0; n < 8; n++) {
            wmma::fragment<wmma::matrix_b, 16, 16, 16, __half, wmma::row_major> b_frag;
            wmma::load_matrix_sync(b_frag, W16 + k * HH + n * 16, HH);
            wmma::mma_sync(c_frag[n], a_frag, b_frag, c_frag[n]);
        }
    }
    float* myC = sC[warp];
    #pragma unroll
    for (int n = 0; n < 8; n++)
        wmma::store_matrix_sync(myC + n * 16, c_frag[n], HH, wmma::mem_row_major);
    __syncwarp();

    // epilogue: 16 rows x 16 col-groups of 8
    for (int gI = lane; gI < 16 * 16; gI += 32) {
        int r = gI >> 4, c8 = gI & 15;
        float o[8];
        #pragma unroll
        for (int q = 0; q < 8; q++) {
            int col = c8 * 8 + q;
            o[q] = fmaxf(myC[r * HH + col] * s_sc[col] + s_sh[col], 0.f);
        }
        __half2 h0 = __floats2half2_rn(o[0], o[1]);
        __half2 h1 = __floats2half2_rn(o[2], o[3]);
        __half2 h2 = __floats2half2_rn(o[4], o[5]);
        __half2 h3 = __floats2half2_rn(o[6], o[7]);
        int4 pk = make_int4(h2i(h0), h2i(h1), h2i(h2), h2i(h3));
        *(int4*)&C16[(long long)(row0 + r) * HH + c8 * 8] = pk;
    }
}

// ---------------- pocket MLP + bilinear weight contraction ---------------------
__global__ void k_small(const float* __restrict__ pf,
                        const float* __restrict__ W1, const float* __restrict__ b1,
                        const float* __restrict__ W2, const float* __restrict__ b2,
                        const float* __restrict__ bilW) {
    __shared__ float t1[64];
    __shared__ float spk[64];
    int tid = threadIdx.x;
    if (tid < 64) {
        float acc = b1[tid];
        for (int k = 0; k < 28; k++) acc += pf[k] * W1[k * 64 + tid];
        t1[tid] = fmaxf(acc, 0.f);
    }
    __syncthreads();
    if (tid < 64) {
        float acc = b2[tid];
        for (int jj = 0; jj < 64; jj++) acc += t1[jj] * W2[jj * 64 + tid];
        spk[tid] = acc;
    }
    __syncthreads();
    for (int idx = tid; idx < 64 * HH; idx += blockDim.x) {
        int o = idx / HH, i2 = idx % HH;
        const float4* wrow = (const float4*)(bilW + ((long long)o * HH + i2) * 64);
        float acc = 0.f;
        #pragma unroll
        for (int jj = 0; jj < 16; jj++) {
            float4 w = __ldg(&wrow[jj]);
            const float4 s = *(const float4*)&spk[jj * 4];
            acc += w.x * s.x + w.y * s.y + w.z * s.z + w.w * s.w;
        }
        g_Wp[o * HH + i2] = acc;
    }
}

// ---------------- pool + bilinear + classifier ---------------------------------
__global__ void k_pool_final(const void* __restrict__ batch,
                             const float* __restrict__ bil_b,
                             const float* __restrict__ cW1, const float* __restrict__ cb1,
                             const float* __restrict__ cW2, const float* __restrict__ cb2,
                             float* __restrict__ out) {
    __shared__ int   sLo, sHi;
    __shared__ float lig[HH];
    __shared__ float inter[64];
    __shared__ float c1[32];
    int g = blockIdx.x;
    int tid = threadIdx.x;   // 64
    int is64 = g_is64;
    if (tid < 2) {
        int key = g + tid;
        int lo = 0, hi = NN;
        while (lo < hi) {
            int mid = (lo + hi) >> 1;
            if (load_idx(batch, mid, is64) < key) lo = mid + 1; else hi = mid;
        }
        if (tid == 0) sLo = lo; else sHi = lo;
    }
    __syncthreads();
    int lo = sLo, hi = sHi;
    float s0 = 0.f, s1 = 0.f;
    for (int r = lo; r < hi; r++) {
        uint u0 = __ldg((const uint*)(g_h16 + (long long)r * HH + tid * 2));
        float2 f0 = __half22float2(*(const __half2*)&u0);
        s0 += f0.x; s1 += f0.y;
    }
    float cnt = fmaxf((float)(hi - lo), 1.f);
    lig[tid * 2]     = s0 / cnt;
    lig[tid * 2 + 1] = s1 / cnt;
    __syncthreads();
    {
        float acc = bil_b[tid];
        const float* wp = &g_Wp[tid * HH];
        #pragma unroll 8
        for (int i = 0; i < HH; i++) acc += lig[i] * wp[i];
        inter[tid] = acc;
    }
    __syncthreads();
    if (tid < 32) {
        float acc = cb1[tid];
        #pragma unroll 8
        for (int o = 0; o < 64; o++) acc += inter[o] * cW1[o * 32 + tid];
        c1[tid] = fmaxf(acc, 0.f);
    }
    __syncthreads();
    if (tid == 0) {
        float acc = cb2[0];
        #pragma unroll
        for (int t = 0; t < 32; t++) acc += c1[t] * cW2[t];
        out[g] = acc;
    }
}

// ---------------- launch ---------------------------------------------------------
extern "C" void kernel_launch(void* const* d_in, const int* in_sizes, int n_in,
                              void* d_out, int out_size) {
    const float* x       = (const float*)d_in[0];
    const void*  ei      = d_in[1];
    const void*  batch   = d_in[2];
    const float* pocket  = (const float*)d_in[3];
    const float* conv0_W = (const float*)d_in[4];
    const float* conv0_b = (const float*)d_in[5];
    const float* convs_W = (const float*)d_in[6];
    const float* convs_b = (const float*)d_in[7];
    const float* bn_g    = (const float*)d_in[8];
    const float* bn_b    = (const float*)d_in[9];
    const float* bn_m    = (const float*)d_in[10];
    const float* bn_v    = (const float*)d_in[11];
    const float* pW1     = (const float*)d_in[12];
    const float* pb1     = (const float*)d_in[13];
    const float* pW2     = (const float*)d_in[14];
    const float* pb2     = (const float*)d_in[15];
    const float* bilW    = (const float*)d_in[16];
    const float* bilb    = (const float*)d_in[17];
    const float* cW1     = (const float*)d_in[18];
    const float* cb1     = (const float*)d_in[19];
    const float* cW2     = (const float*)d_in[20];
    const float* cb2     = (const float*)d_in[21];
    float* out = (float*)d_out;

    __half* h16 = nullptr; __half* u16 = nullptr; __half* w16 = nullptr; int* degp = nullptr;
    cudaGetSymbolAddress((void**)&h16, g_h16);
    cudaGetSymbolAddress((void**)&u16, g_u16);
    cudaGetSymbolAddress((void**)&w16, g_W16);
    cudaGetSymbolAddress((void**)&degp, g_deg);

    const int TB = 256;
    // CSR build + input/weight prep
    k_detect<<<1, 32>>>(ei);
    k_small<<<1, 256>>>(pocket, pW1, pb1, pW2, pb2, bilW);
    k_prep_x<<<(NN + TB - 1) / TB, TB>>>(x);
    k_w16<<<(2 * HH * HH + TB - 1) / TB, TB>>>(convs_W);
    cudaMemsetAsync(degp, 0, NN * sizeof(int));
    k_deg_count<<<(NE / 4 + TB - 1) / TB, TB>>>(ei);
    k_scanA<<<NB, 1024>>>();
    k_scanB<<<1, 32>>>();
    k_scanC<<<NB, 1024>>>();
    k_scatter<<<(NE / 4 + TB - 1) / TB, TB>>>(ei);

    int agg_blocks = (NN * 32 + TB - 1) / TB;

    // layer 0: aggregate x (7-dim) then GEMM+BN+ReLU
    k_aggx<<<(NN + TB - 1) / TB, TB>>>();
    k_gemm0<<<(NN + 31) / 32, HH>>>(conv0_W, conv0_b, bn_g, bn_b, bn_m, bn_v);
    // layers 1,2: aggregate then tensor-core GEMM
    for (int l = 1; l <= 2; l++) {
        const __half* Wl = w16 + (long long)(l - 1) * HH * HH;
        const float* b = convs_b + (l - 1) * HH;
        k_agg<<<agg_blocks, TB>>>(h16, u16);
        k_gemm_tc<<<NP / 64, 128>>>(u16, Wl, h16, b,
                                    bn_g + l * HH, bn_b + l * HH,
                                    bn_m + l * HH, bn_v + l * HH);
    }

    // pool + bilinear + classifier
    k_pool_final<<<GG, 64>>>(batch, bilb, cW1, cb1, cW2, cb2, out);
}